// round 7
// baseline (speedup 1.0000x reference)
#include <cuda_runtime.h>
#include <cuda_bf16.h>
#include <cstdint>

// Problem shapes (fixed by the dataset).
#define BB 2
#define TT 2048
#define DD 1024
#define HH 16
#define DKK 64
#define MTOT (BB*TT)     // 4096 rows
#define NQKV 1152        // fused projection width: 1024 Q + 64 K + 64 V

// ---------------------------------------------------------------------------
// Device scratch (allocation-free per harness rules).
// ---------------------------------------------------------------------------
__device__ unsigned short g_QKVh[MTOT * NQKV], g_QKVl[MTOT * NQKV]; // QKV bf16 hi/lo
__device__ unsigned short g_xhi[MTOT * DD], g_xlo[MTOT * DD];    // x as bf16 hi/lo
__device__ unsigned short g_Bhi[NQKV * DD], g_Blo[NQKV * DD];    // [Wq;Wk;Wv]^T bf16
__device__ unsigned short g_Yhi[MTOT * DD], g_Ylo[MTOT * DD];    // Y as bf16 hi/lo
__device__ unsigned short g_Wohi[DD * DD], g_Wolo[DD * DD];      // Wo^T bf16

// ---------------------------------------------------------------------------
// Generic-PTX tensor helpers (NO arch-'a' features: work on plain sm_103).
// ---------------------------------------------------------------------------
__device__ __forceinline__ uint32_t smem_u32(const void* p) {
    uint32_t a;
    asm("{ .reg .u64 t; cvta.to.shared.u64 t, %1; cvt.u32.u64 %0, t; }"
        : "=r"(a) : "l"(p));
    return a;
}

__device__ __forceinline__ void ldsm_x4(uint32_t& r0, uint32_t& r1,
                                        uint32_t& r2, uint32_t& r3, uint32_t a) {
    asm volatile("ldmatrix.sync.aligned.m8n8.x4.shared.b16 {%0,%1,%2,%3}, [%4];"
                 : "=r"(r0), "=r"(r1), "=r"(r2), "=r"(r3) : "r"(a));
}
__device__ __forceinline__ void ldsm_x4_t(uint32_t& r0, uint32_t& r1,
                                          uint32_t& r2, uint32_t& r3, uint32_t a) {
    asm volatile("ldmatrix.sync.aligned.m8n8.x4.trans.shared.b16 {%0,%1,%2,%3}, [%4];"
                 : "=r"(r0), "=r"(r1), "=r"(r2), "=r"(r3) : "r"(a));
}

__device__ __forceinline__ void mma_bf16(float* d, const uint32_t* a,
                                         const uint32_t* b) {
    asm volatile(
        "mma.sync.aligned.m16n8k16.row.col.f32.bf16.bf16.f32 "
        "{%0,%1,%2,%3}, {%4,%5,%6,%7}, {%8,%9}, {%0,%1,%2,%3};"
        : "+f"(d[0]), "+f"(d[1]), "+f"(d[2]), "+f"(d[3])
        : "r"(a[0]), "r"(a[1]), "r"(a[2]), "r"(a[3]), "r"(b[0]), "r"(b[1]));
}

__device__ __forceinline__ void cp_async16(uint32_t saddr, const void* g) {
    asm volatile("cp.async.cg.shared.global [%0], [%1], 16;" :: "r"(saddr), "l"(g));
}
#define CP_COMMIT() asm volatile("cp.async.commit_group;" ::: "memory")
#define CP_WAIT(n)  asm volatile("cp.async.wait_group %0;" :: "n"(n) : "memory")

// Split two fp32 into packed bf16x2 hi & lo parts (low half = first element).
__device__ __forceinline__ void split2(float a, float b, uint32_t& hi, uint32_t& lo) {
    __nv_bfloat16 ha = __float2bfloat16(a), hb = __float2bfloat16(b);
    __nv_bfloat16 la = __float2bfloat16(a - __bfloat162float(ha));
    __nv_bfloat16 lb = __float2bfloat16(b - __bfloat162float(hb));
    __nv_bfloat162 H = __halves2bfloat162(ha, hb);
    __nv_bfloat162 L = __halves2bfloat162(la, lb);
    hi = *reinterpret_cast<uint32_t*>(&H);
    lo = *reinterpret_cast<uint32_t*>(&L);
}

// ---------------------------------------------------------------------------
// Conversion kernels: fp32 -> bf16 hi/lo split.
// ---------------------------------------------------------------------------
__global__ __launch_bounds__(256) void conv_split(
    const float4* __restrict__ a, __nv_bfloat162* __restrict__ hi,
    __nv_bfloat162* __restrict__ lo, int n4)
{
    int i = blockIdx.x * blockDim.x + threadIdx.x;
    if (i >= n4) return;
    float4 v = a[i];
    __nv_bfloat16 h0 = __float2bfloat16(v.x), h1 = __float2bfloat16(v.y);
    __nv_bfloat16 h2 = __float2bfloat16(v.z), h3 = __float2bfloat16(v.w);
    __nv_bfloat16 l0 = __float2bfloat16(v.x - __bfloat162float(h0));
    __nv_bfloat16 l1 = __float2bfloat16(v.y - __bfloat162float(h1));
    __nv_bfloat16 l2 = __float2bfloat16(v.z - __bfloat162float(h2));
    __nv_bfloat16 l3 = __float2bfloat16(v.w - __bfloat162float(h3));
    hi[2*i]   = __halves2bfloat162(h0, h1);
    hi[2*i+1] = __halves2bfloat162(h2, h3);
    lo[2*i]   = __halves2bfloat162(l0, l1);
    lo[2*i+1] = __halves2bfloat162(l2, l3);
}

// Transpose + split: W[K=1024, N] row-major -> out[(n_off+n)*1024 + k] bf16 hi/lo.
__global__ __launch_bounds__(256) void convT_split(
    const float* __restrict__ W, int N,
    __nv_bfloat16* __restrict__ oh, __nv_bfloat16* __restrict__ ol, int n_off)
{
    __shared__ float t[32][33];
    const int k0 = blockIdx.y * 32, n0 = blockIdx.x * 32;
    const int tx = threadIdx.x & 31, ty = threadIdx.x >> 5;  // 32 x 8
#pragma unroll
    for (int j = 0; j < 4; ++j)
        t[ty + 8*j][tx] = W[(size_t)(k0 + ty + 8*j) * N + n0 + tx];
    __syncthreads();
#pragma unroll
    for (int j = 0; j < 4; ++j) {
        float v = t[tx][ty + 8*j];   // = W[k0+tx][n0+ty+8j]
        __nv_bfloat16 h = __float2bfloat16(v);
        __nv_bfloat16 l = __float2bfloat16(v - __bfloat162float(h));
        size_t o = (size_t)(n_off + n0 + ty + 8*j) * 1024 + k0 + tx;
        oh[o] = h; ol[o] = l;
    }
}

// ---------------------------------------------------------------------------
// Split-bf16 tensor-core GEMM via mma.sync. CTA tile 128x128, 8 warps
// (each 32x64), K-stage 32, cp.async double buffer, rows padded to 80B.
// 2 CTAs/SM (smem 81920 B x2 = 163KB). Fused hi/lo output when SPLIT_OUT.
// ---------------------------------------------------------------------------
#define ROWB 80                 // 32 bf16 = 64B data + 16B pad
#define ARR_B (128 * ROWB)      // 10240 B
#define STAGE_B (4 * ARR_B)     // 40960 B (Ahi, Alo, Bhi, Blo)
#define GEMM_SMEM_BYTES (2 * STAGE_B)   // 81920 B

template<bool SPLIT_OUT>
__global__ __launch_bounds__(256, 2) void gemm_split_mma(
    const __nv_bfloat16* __restrict__ Ah, const __nv_bfloat16* __restrict__ Al,
    const __nv_bfloat16* __restrict__ Bh, const __nv_bfloat16* __restrict__ Bl,
    float* __restrict__ C, __nv_bfloat16* __restrict__ Ch,
    __nv_bfloat16* __restrict__ Cl, int Kd, int ldc)
{
    extern __shared__ __align__(16) char smd[];
    const uint32_t sbase = smem_u32(smd);
    const int tid  = threadIdx.x;
    const int lane = tid & 31;
    const int w    = tid >> 5;
    const int m0 = blockIdx.y * 128;
    const int n0 = blockIdx.x * 128;
    const int mw = (w >> 1) * 32;
    const int nw = (w & 1) * 64;

    const __nv_bfloat16* gsrc[4] = {Ah, Al, Bh, Bl};

    float acc[2][8][4];
#pragma unroll
    for (int mt = 0; mt < 2; ++mt)
#pragma unroll
        for (int n8 = 0; n8 < 8; ++n8)
#pragma unroll
            for (int q = 0; q < 4; ++q) acc[mt][n8][q] = 0.f;

    const int NS = Kd >> 5;   // K-stages of 32

    // --- stage loader: 2048 x 16B chunks, 8 per thread ---
    auto load_stage = [&](int s) {
        const int kt = s << 5;
        const uint32_t sb = sbase + (s & 1) * STAGE_B;
#pragma unroll
        for (int v = 0; v < 8; ++v) {
            int idx = v * 256 + tid;
            int arr = idx >> 9;          // 0..3
            int r   = (idx >> 2) & 127;
            int c   = idx & 3;
            int grow = (arr < 2 ? m0 : n0) + r;
            const __nv_bfloat16* gp = gsrc[arr] + (size_t)grow * Kd + kt + c * 8;
            cp_async16(sb + arr * ARR_B + r * ROWB + c * 16, gp);
        }
    };

    load_stage(0);
    CP_COMMIT();

    for (int s = 0; s < NS; ++s) {
        if (s + 1 < NS) { load_stage(s + 1); CP_COMMIT(); CP_WAIT(1); }
        else            { CP_WAIT(0); }
        __syncthreads();

        const uint32_t sb = sbase + (s & 1) * STAGE_B;
        const uint32_t aHb = sb + (mw + (lane & 15)) * ROWB + (lane >> 4) * 16;
        const uint32_t aLb = aHb + ARR_B;
        const uint32_t bRow = nw + ((lane >> 4) << 3) + (lane & 7);
        const uint32_t bHb = sb + 2 * ARR_B + bRow * ROWB + ((lane >> 3) & 1) * 16;
        const uint32_t bLb = bHb + ARR_B;

#pragma unroll
        for (int kk = 0; kk < 2; ++kk) {
            const uint32_t ko = kk * 32;       // 16 halfs = 32B
            uint32_t ah[2][4], al[2][4];
            ldsm_x4(ah[0][0], ah[0][1], ah[0][2], ah[0][3], aHb + ko);
            ldsm_x4(ah[1][0], ah[1][1], ah[1][2], ah[1][3], aHb + 16 * ROWB + ko);
            ldsm_x4(al[0][0], al[0][1], al[0][2], al[0][3], aLb + ko);
            ldsm_x4(al[1][0], al[1][1], al[1][2], al[1][3], aLb + 16 * ROWB + ko);

            uint32_t bh[8][2];
#pragma unroll
            for (int g = 0; g < 4; ++g)
                ldsm_x4(bh[2*g][0], bh[2*g][1], bh[2*g+1][0], bh[2*g+1][1],
                        bHb + g * 16 * ROWB + ko);
#pragma unroll
            for (int mt = 0; mt < 2; ++mt)
#pragma unroll
                for (int n8 = 0; n8 < 8; ++n8)
                    mma_bf16(acc[mt][n8], ah[mt], bh[n8]);   // hi*hi
#pragma unroll
            for (int mt = 0; mt < 2; ++mt)
#pragma unroll
                for (int n8 = 0; n8 < 8; ++n8)
                    mma_bf16(acc[mt][n8], al[mt], bh[n8]);   // lo*hi

            uint32_t bl[8][2];
#pragma unroll
            for (int g = 0; g < 4; ++g)
                ldsm_x4(bl[2*g][0], bl[2*g][1], bl[2*g+1][0], bl[2*g+1][1],
                        bLb + g * 16 * ROWB + ko);
#pragma unroll
            for (int mt = 0; mt < 2; ++mt)
#pragma unroll
                for (int n8 = 0; n8 < 8; ++n8)
                    mma_bf16(acc[mt][n8], ah[mt], bl[n8]);   // hi*lo
        }
        __syncthreads();
    }

    // Epilogue
#pragma unroll
    for (int mt = 0; mt < 2; ++mt) {
        const int row = m0 + mw + mt * 16 + (lane >> 2);
        const int col = n0 + nw + (lane & 3) * 2;
        if (SPLIT_OUT) {
            __nv_bfloat16* h0 = Ch + (size_t)row * ldc + col;
            __nv_bfloat16* h1 = Ch + (size_t)(row + 8) * ldc + col;
            __nv_bfloat16* l0 = Cl + (size_t)row * ldc + col;
            __nv_bfloat16* l1 = Cl + (size_t)(row + 8) * ldc + col;
#pragma unroll
            for (int n8 = 0; n8 < 8; ++n8) {
                uint32_t hh, ll;
                split2(acc[mt][n8][0], acc[mt][n8][1], hh, ll);
                *(uint32_t*)(h0 + n8 * 8) = hh;
                *(uint32_t*)(l0 + n8 * 8) = ll;
                split2(acc[mt][n8][2], acc[mt][n8][3], hh, ll);
                *(uint32_t*)(h1 + n8 * 8) = hh;
                *(uint32_t*)(l1 + n8 * 8) = ll;
            }
        } else {
            float* c0 = C + (size_t)row * ldc + col;
            float* c1 = C + (size_t)(row + 8) * ldc + col;
#pragma unroll
            for (int n8 = 0; n8 < 8; ++n8) {
                *(float2*)(c0 + n8 * 8) = make_float2(acc[mt][n8][0], acc[mt][n8][1]);
                *(float2*)(c1 + n8 * 8) = make_float2(acc[mt][n8][2], acc[mt][n8][3]);
            }
        }
    }
}

// ---------------------------------------------------------------------------
// Tensor-core flash attention (causal, multi-query, split-bf16 precision).
// Q tile 128x64 per CTA, 8 warps x 16 rows; K/V tiles 64x64 double-buffered.
// Softmax entirely register-resident. Epilogue emits Y as bf16 hi/lo (fused).
// ---------------------------------------------------------------------------
#define FT_ROWB 144
#define FT_ARR  (64 * FT_ROWB)
#define FT_STG  (4 * FT_ARR)
#define FT_SMEM (2 * FT_STG)

__global__ __launch_bounds__(256) void flash_tc(
    const __nv_bfloat16* __restrict__ QKVh,
    const __nv_bfloat16* __restrict__ QKVl,
    __nv_bfloat16* __restrict__ Yh, __nv_bfloat16* __restrict__ Yl)
{
    extern __shared__ __align__(16) char smd[];
    const uint32_t sbase = smem_u32(smd);
    const int tid = threadIdx.x, lane = tid & 31, wid = tid >> 5;
    const int h = blockIdx.y, b = blockIdx.z;
    const int qb = (int)gridDim.x - 1 - (int)blockIdx.x;   // longest first
    const int i0 = qb * 128;
    const int g = lane >> 2, qd = lane & 3;

    uint32_t qh[4][4], ql[4][4];
    {
        const int r0 = i0 + wid * 16 + g;
        const size_t b0 = (size_t)(b * TT + r0) * NQKV + h * 64;
        const size_t b1 = b0 + (size_t)8 * NQKV;
#pragma unroll
        for (int t = 0; t < 4; ++t) {
            const int c = t * 16 + qd * 2;
            qh[t][0] = *(const uint32_t*)(QKVh + b0 + c);
            qh[t][1] = *(const uint32_t*)(QKVh + b1 + c);
            qh[t][2] = *(const uint32_t*)(QKVh + b0 + c + 8);
            qh[t][3] = *(const uint32_t*)(QKVh + b1 + c + 8);
            ql[t][0] = *(const uint32_t*)(QKVl + b0 + c);
            ql[t][1] = *(const uint32_t*)(QKVl + b1 + c);
            ql[t][2] = *(const uint32_t*)(QKVl + b0 + c + 8);
            ql[t][3] = *(const uint32_t*)(QKVl + b1 + c + 8);
        }
    }

    float o[8][4];
#pragma unroll
    for (int n8 = 0; n8 < 8; ++n8)
#pragma unroll
        for (int c = 0; c < 4; ++c) o[n8][c] = 0.f;
    float m0 = -1e30f, m1 = -1e30f, l0 = 0.f, l1 = 0.f;

    auto load_kv = [&](int it) {
        const int j0 = it * 64;
        const uint32_t sb = sbase + (it & 1) * FT_STG;
#pragma unroll
        for (int v = 0; v < 8; ++v) {
            int idx = v * 256 + tid;
            int arr = idx >> 9, r = (idx >> 3) & 63, c = idx & 7;
            const __nv_bfloat16* src = (arr & 1) ? QKVl : QKVh;
            int col = (arr < 2 ? 1024 : 1088) + c * 8;
            cp_async16(sb + arr * FT_ARR + r * FT_ROWB + c * 16,
                       src + (size_t)(b * TT + j0 + r) * NQKV + col);
        }
    };

    load_kv(0);
    CP_COMMIT();

    const int nIter = 2 * qb + 2;
    for (int it = 0; it < nIter; ++it) {
        if (it + 1 < nIter) { load_kv(it + 1); CP_COMMIT(); CP_WAIT(1); }
        else                { CP_WAIT(0); }
        __syncthreads();

        const uint32_t sb = sbase + (it & 1) * FT_STG;

        float s[8][4];
#pragma unroll
        for (int n8 = 0; n8 < 8; ++n8)
#pragma unroll
            for (int c = 0; c < 4; ++c) s[n8][c] = 0.f;

        const uint32_t kA = sb + (((lane >> 4) << 3) + (lane & 7)) * FT_ROWB
                          + ((lane >> 3) & 1) * 16;
#pragma unroll
        for (int t = 0; t < 4; ++t) {
            uint32_t kh[8][2];
#pragma unroll
            for (int gg = 0; gg < 4; ++gg)
                ldsm_x4(kh[2*gg][0], kh[2*gg][1], kh[2*gg+1][0], kh[2*gg+1][1],
                        kA + gg * 16 * FT_ROWB + t * 32);
#pragma unroll
            for (int n8 = 0; n8 < 8; ++n8) mma_bf16(s[n8], qh[t], kh[n8]);
#pragma unroll
            for (int n8 = 0; n8 < 8; ++n8) mma_bf16(s[n8], ql[t], kh[n8]);
            uint32_t kl[8][2];
#pragma unroll
            for (int gg = 0; gg < 4; ++gg)
                ldsm_x4(kl[2*gg][0], kl[2*gg][1], kl[2*gg+1][0], kl[2*gg+1][1],
                        kA + FT_ARR + gg * 16 * FT_ROWB + t * 32);
#pragma unroll
            for (int n8 = 0; n8 < 8; ++n8) mma_bf16(s[n8], qh[t], kl[n8]);
        }

        const int j0 = it * 64;
        const int r0 = i0 + wid * 16 + g;
        const bool msk = (j0 + 63 > i0 + wid * 16);
#pragma unroll
        for (int n8 = 0; n8 < 8; ++n8) {
#pragma unroll
            for (int c = 0; c < 4; ++c) s[n8][c] *= 0.125f;
            if (msk) {
                const int j = j0 + n8 * 8 + qd * 2;
                if (j     > r0)     s[n8][0] = -1e30f;
                if (j + 1 > r0)     s[n8][1] = -1e30f;
                if (j     > r0 + 8) s[n8][2] = -1e30f;
                if (j + 1 > r0 + 8) s[n8][3] = -1e30f;
            }
        }

        float mx0 = -1e30f, mx1 = -1e30f;
#pragma unroll
        for (int n8 = 0; n8 < 8; ++n8) {
            mx0 = fmaxf(mx0, fmaxf(s[n8][0], s[n8][1]));
            mx1 = fmaxf(mx1, fmaxf(s[n8][2], s[n8][3]));
        }
        mx0 = fmaxf(mx0, __shfl_xor_sync(0xffffffffu, mx0, 1));
        mx0 = fmaxf(mx0, __shfl_xor_sync(0xffffffffu, mx0, 2));
        mx1 = fmaxf(mx1, __shfl_xor_sync(0xffffffffu, mx1, 1));
        mx1 = fmaxf(mx1, __shfl_xor_sync(0xffffffffu, mx1, 2));
        const float mn0 = fmaxf(m0, mx0), mn1 = fmaxf(m1, mx1);
        const float sc0 = __expf(m0 - mn0), sc1 = __expf(m1 - mn1);
        m0 = mn0; m1 = mn1;

        float sum0 = 0.f, sum1 = 0.f;
        uint32_t ph[4][4], pl[4][4];
#pragma unroll
        for (int t = 0; t < 4; ++t) {
            float p00 = __expf(s[2*t][0] - mn0),   p01 = __expf(s[2*t][1] - mn0);
            float p02 = __expf(s[2*t][2] - mn1),   p03 = __expf(s[2*t][3] - mn1);
            float p10 = __expf(s[2*t+1][0] - mn0), p11 = __expf(s[2*t+1][1] - mn0);
            float p12 = __expf(s[2*t+1][2] - mn1), p13 = __expf(s[2*t+1][3] - mn1);
            sum0 += p00 + p01 + p10 + p11;
            sum1 += p02 + p03 + p12 + p13;
            split2(p00, p01, ph[t][0], pl[t][0]);
            split2(p02, p03, ph[t][1], pl[t][1]);
            split2(p10, p11, ph[t][2], pl[t][2]);
            split2(p12, p13, ph[t][3], pl[t][3]);
        }
        sum0 += __shfl_xor_sync(0xffffffffu, sum0, 1);
        sum0 += __shfl_xor_sync(0xffffffffu, sum0, 2);
        sum1 += __shfl_xor_sync(0xffffffffu, sum1, 1);
        sum1 += __shfl_xor_sync(0xffffffffu, sum1, 2);
        l0 = l0 * sc0 + sum0;
        l1 = l1 * sc1 + sum1;
#pragma unroll
        for (int n8 = 0; n8 < 8; ++n8) {
            o[n8][0] *= sc0; o[n8][1] *= sc0;
            o[n8][2] *= sc1; o[n8][3] *= sc1;
        }

        const uint32_t vA = sb + 2 * FT_ARR
                          + ((lane & 7) + ((lane >> 3) & 1) * 8) * FT_ROWB
                          + (lane >> 4) * 16;
#pragma unroll
        for (int t = 0; t < 4; ++t) {
            uint32_t vh[8][2];
#pragma unroll
            for (int dg = 0; dg < 4; ++dg)
                ldsm_x4_t(vh[2*dg][0], vh[2*dg][1], vh[2*dg+1][0], vh[2*dg+1][1],
                          vA + t * 16 * FT_ROWB + dg * 32);
#pragma unroll
            for (int n8 = 0; n8 < 8; ++n8) mma_bf16(o[n8], ph[t], vh[n8]);
#pragma unroll
            for (int n8 = 0; n8 < 8; ++n8) mma_bf16(o[n8], pl[t], vh[n8]);
            uint32_t vl[8][2];
#pragma unroll
            for (int dg = 0; dg < 4; ++dg)
                ldsm_x4_t(vl[2*dg][0], vl[2*dg][1], vl[2*dg+1][0], vl[2*dg+1][1],
                          vA + FT_ARR + t * 16 * FT_ROWB + dg * 32);
#pragma unroll
            for (int n8 = 0; n8 < 8; ++n8) mma_bf16(o[n8], ph[t], vl[n8]);
        }
        __syncthreads();
    }

    // ---- epilogue: normalize and write Y as bf16 hi/lo (fused split) ----
    const float inv0 = 1.f / l0, inv1 = 1.f / l1;
    const int r0 = i0 + wid * 16 + g;
    const size_t off0 = (size_t)(b * TT + r0) * DD + h * 64 + qd * 2;
    const size_t off1 = off0 + (size_t)8 * DD;
#pragma unroll
    for (int n8 = 0; n8 < 8; ++n8) {
        uint32_t hh, ll;
        split2(o[n8][0] * inv0, o[n8][1] * inv0, hh, ll);
        *(uint32_t*)(Yh + off0 + n8 * 8) = hh;
        *(uint32_t*)(Yl + off0 + n8 * 8) = ll;
        split2(o[n8][2] * inv1, o[n8][3] * inv1, hh, ll);
        *(uint32_t*)(Yh + off1 + n8 * 8) = hh;
        *(uint32_t*)(Yl + off1 + n8 * 8) = ll;
    }
}

// ---------------------------------------------------------------------------
extern "C" void kernel_launch(void* const* d_in, const int* in_sizes, int n_in,
                              void* d_out, int out_size)
{
    (void)in_sizes; (void)n_in; (void)out_size;
    const float* x  = (const float*)d_in[0];
    const float* Wq = (const float*)d_in[1];
    const float* Wk = (const float*)d_in[2];
    const float* Wv = (const float*)d_in[3];
    const float* Wo = (const float*)d_in[4];
    float* out = (float*)d_out;

    unsigned short *qkvh, *qkvl, *xh, *xl, *Bh, *Bl, *Yh, *Yl, *Woh, *Wol;
    cudaGetSymbolAddress((void**)&qkvh, g_QKVh);
    cudaGetSymbolAddress((void**)&qkvl, g_QKVl);
    cudaGetSymbolAddress((void**)&xh, g_xhi);
    cudaGetSymbolAddress((void**)&xl, g_xlo);
    cudaGetSymbolAddress((void**)&Bh, g_Bhi);
    cudaGetSymbolAddress((void**)&Bl, g_Blo);
    cudaGetSymbolAddress((void**)&Yh, g_Yhi);
    cudaGetSymbolAddress((void**)&Yl, g_Ylo);
    cudaGetSymbolAddress((void**)&Woh, g_Wohi);
    cudaGetSymbolAddress((void**)&Wol, g_Wolo);

    cudaFuncSetAttribute(gemm_split_mma<true>,
                         cudaFuncAttributeMaxDynamicSharedMemorySize, GEMM_SMEM_BYTES);
    cudaFuncSetAttribute(gemm_split_mma<false>,
                         cudaFuncAttributeMaxDynamicSharedMemorySize, GEMM_SMEM_BYTES);
    cudaFuncSetAttribute(flash_tc,
                         cudaFuncAttributeMaxDynamicSharedMemorySize, FT_SMEM);

    const int n4x = MTOT * DD / 4;

    // 1) Split x -> bf16 hi/lo
    conv_split<<<n4x / 256, 256>>>((const float4*)x,
        (__nv_bfloat162*)xh, (__nv_bfloat162*)xl, n4x);

    // 2) Transpose+split weights into fused B [N=1152, K=1024] (+ Wo^T)
    convT_split<<<dim3(32, 32), 256>>>(Wq, 1024, (__nv_bfloat16*)Bh, (__nv_bfloat16*)Bl, 0);
    convT_split<<<dim3(2, 32),  256>>>(Wk, 64,   (__nv_bfloat16*)Bh, (__nv_bfloat16*)Bl, 1024);
    convT_split<<<dim3(2, 32),  256>>>(Wv, 64,   (__nv_bfloat16*)Bh, (__nv_bfloat16*)Bl, 1088);
    convT_split<<<dim3(32, 32), 256>>>(Wo, 1024, (__nv_bfloat16*)Woh, (__nv_bfloat16*)Wol, 0);

    // 3) Fused QKV projection, epilogue emits bf16 hi/lo directly
    gemm_split_mma<true><<<dim3(NQKV / 128, MTOT / 128), 256, GEMM_SMEM_BYTES>>>(
        (const __nv_bfloat16*)xh, (const __nv_bfloat16*)xl,
        (const __nv_bfloat16*)Bh, (const __nv_bfloat16*)Bl,
        nullptr, (__nv_bfloat16*)qkvh, (__nv_bfloat16*)qkvl, DD, NQKV);

    // 4) Tensor-core causal multi-query flash attention -> Yh/Yl (fused split)
    flash_tc<<<dim3(TT / 128, HH, BB), 256, FT_SMEM>>>(
        (const __nv_bfloat16*)qkvh, (const __nv_bfloat16*)qkvl,
        (__nv_bfloat16*)Yh, (__nv_bfloat16*)Yl);

    // 5) Output projection: out = Y @ Wo (fp32 epilogue)
    gemm_split_mma<false><<<dim3(DD / 128, MTOT / 128), 256, GEMM_SMEM_BYTES>>>(
        (const __nv_bfloat16*)Yh, (const __nv_bfloat16*)Yl,
        (const __nv_bfloat16*)Woh, (const __nv_bfloat16*)Wol,
        out, nullptr, nullptr, DD, DD);
}

// round 8
// speedup vs baseline: 1.4023x; 1.4023x over previous
#include <cuda_runtime.h>
#include <cuda_fp16.h>
#include <cstdint>

// Problem shapes (fixed by the dataset).
#define BB 2
#define TT 2048
#define DD 1024
#define HH 16
#define DKK 64
#define MTOT (BB*TT)     // 4096 rows
#define NQKV 1152        // fused projection width: 1024 Q + 64 K + 64 V

// ---------------------------------------------------------------------------
// Device scratch (allocation-free per harness rules).  All fp16 now.
// ---------------------------------------------------------------------------
__device__ unsigned short g_QKVh[MTOT * NQKV], g_QKVl[MTOT * NQKV]; // QKV fp16 hi/lo
__device__ unsigned short g_xhi[MTOT * DD], g_xlo[MTOT * DD];    // x fp16 hi/lo
__device__ unsigned short g_Bhi[NQKV * DD];                      // [Wq;Wk;Wv]^T fp16 hi
__device__ unsigned short g_Yhi[MTOT * DD], g_Ylo[MTOT * DD];    // Y fp16 hi/lo
__device__ unsigned short g_Wohi[DD * DD];                       // Wo^T fp16 hi

// ---------------------------------------------------------------------------
// Generic-PTX tensor helpers (NO arch-'a' features: work on plain sm_103).
// ---------------------------------------------------------------------------
__device__ __forceinline__ uint32_t smem_u32(const void* p) {
    uint32_t a;
    asm("{ .reg .u64 t; cvta.to.shared.u64 t, %1; cvt.u32.u64 %0, t; }"
        : "=r"(a) : "l"(p));
    return a;
}

__device__ __forceinline__ void ldsm_x4(uint32_t& r0, uint32_t& r1,
                                        uint32_t& r2, uint32_t& r3, uint32_t a) {
    asm volatile("ldmatrix.sync.aligned.m8n8.x4.shared.b16 {%0,%1,%2,%3}, [%4];"
                 : "=r"(r0), "=r"(r1), "=r"(r2), "=r"(r3) : "r"(a));
}
__device__ __forceinline__ void ldsm_x4_t(uint32_t& r0, uint32_t& r1,
                                          uint32_t& r2, uint32_t& r3, uint32_t a) {
    asm volatile("ldmatrix.sync.aligned.m8n8.x4.trans.shared.b16 {%0,%1,%2,%3}, [%4];"
                 : "=r"(r0), "=r"(r1), "=r"(r2), "=r"(r3) : "r"(a));
}

// fp16 tensor-core MMA, fp32 accumulate.
__device__ __forceinline__ void mma_f16(float* d, const uint32_t* a,
                                        const uint32_t* b) {
    asm volatile(
        "mma.sync.aligned.m16n8k16.row.col.f32.f16.f16.f32 "
        "{%0,%1,%2,%3}, {%4,%5,%6,%7}, {%8,%9}, {%0,%1,%2,%3};"
        : "+f"(d[0]), "+f"(d[1]), "+f"(d[2]), "+f"(d[3])
        : "r"(a[0]), "r"(a[1]), "r"(a[2]), "r"(a[3]), "r"(b[0]), "r"(b[1]));
}

__device__ __forceinline__ void cp_async16(uint32_t saddr, const void* g) {
    asm volatile("cp.async.cg.shared.global [%0], [%1], 16;" :: "r"(saddr), "l"(g));
}
#define CP_COMMIT() asm volatile("cp.async.commit_group;" ::: "memory")
#define CP_WAIT(n)  asm volatile("cp.async.wait_group %0;" :: "n"(n) : "memory")

// Split two fp32 into packed fp16x2 hi & lo parts (low half = first element).
__device__ __forceinline__ void split2h(float a, float b, uint32_t& hi, uint32_t& lo) {
    __half ha = __float2half(a), hb = __float2half(b);
    __half la = __float2half(a - __half2float(ha));
    __half lb = __float2half(b - __half2float(hb));
    __half2 H = __halves2half2(ha, hb);
    __half2 L = __halves2half2(la, lb);
    hi = *reinterpret_cast<uint32_t*>(&H);
    lo = *reinterpret_cast<uint32_t*>(&L);
}

// ---------------------------------------------------------------------------
// Conversion kernels.
// ---------------------------------------------------------------------------
__global__ __launch_bounds__(256) void conv_split(
    const float4* __restrict__ a, __half2* __restrict__ hi,
    __half2* __restrict__ lo, int n4)
{
    int i = blockIdx.x * blockDim.x + threadIdx.x;
    if (i >= n4) return;
    float4 v = a[i];
    uint32_t h0, l0, h1, l1;
    split2h(v.x, v.y, h0, l0);
    split2h(v.z, v.w, h1, l1);
    ((uint32_t*)hi)[2*i]   = h0;
    ((uint32_t*)hi)[2*i+1] = h1;
    ((uint32_t*)lo)[2*i]   = l0;
    ((uint32_t*)lo)[2*i+1] = l1;
}

// Transpose + round: W[K=1024, N] row-major -> oh[(n_off+n)*1024 + k] fp16 (hi only).
__global__ __launch_bounds__(256) void convT_h(
    const float* __restrict__ W, int N,
    __half* __restrict__ oh, int n_off)
{
    __shared__ float t[32][33];
    const int k0 = blockIdx.y * 32, n0 = blockIdx.x * 32;
    const int tx = threadIdx.x & 31, ty = threadIdx.x >> 5;  // 32 x 8
#pragma unroll
    for (int j = 0; j < 4; ++j)
        t[ty + 8*j][tx] = W[(size_t)(k0 + ty + 8*j) * N + n0 + tx];
    __syncthreads();
#pragma unroll
    for (int j = 0; j < 4; ++j) {
        float v = t[tx][ty + 8*j];   // = W[k0+tx][n0+ty+8j]
        oh[(size_t)(n_off + n0 + ty + 8*j) * 1024 + k0 + tx] = __float2half(v);
    }
}

// ---------------------------------------------------------------------------
// 2-pass fp16 split GEMM via mma.sync: C = (Ah+Al) * Bh^T.
// CTA tile 128x128, 8 warps (each 32x64), K-stage 32, cp.async double buffer.
// Smem: 3 arrays (Ah, Al, Bh), rows padded to 80B. 2 CTAs/SM.
// ---------------------------------------------------------------------------
#define ROWB 80                 // 32 fp16 = 64B data + 16B pad
#define ARR_B (128 * ROWB)      // 10240 B
#define STAGE_B (3 * ARR_B)     // 30720 B (Ah, Al, Bh)
#define GEMM_SMEM_BYTES (2 * STAGE_B)   // 61440 B

template<bool SPLIT_OUT>
__global__ __launch_bounds__(256, 2) void gemm_split_mma(
    const __half* __restrict__ Ah, const __half* __restrict__ Al,
    const __half* __restrict__ Bh,
    float* __restrict__ C, __half* __restrict__ Ch,
    __half* __restrict__ Cl, int Kd, int ldc)
{
    extern __shared__ __align__(16) char smd[];
    const uint32_t sbase = smem_u32(smd);
    const int tid  = threadIdx.x;
    const int lane = tid & 31;
    const int w    = tid >> 5;
    const int m0 = blockIdx.y * 128;
    const int n0 = blockIdx.x * 128;
    const int mw = (w >> 1) * 32;
    const int nw = (w & 1) * 64;

    const __half* gsrc[3] = {Ah, Al, Bh};

    float acc[2][8][4];
#pragma unroll
    for (int mt = 0; mt < 2; ++mt)
#pragma unroll
        for (int n8 = 0; n8 < 8; ++n8)
#pragma unroll
            for (int q = 0; q < 4; ++q) acc[mt][n8][q] = 0.f;

    const int NS = Kd >> 5;   // K-stages of 32

    // --- stage loader: 1536 x 16B chunks, 6 per thread ---
    auto load_stage = [&](int s) {
        const int kt = s << 5;
        const uint32_t sb = sbase + (s & 1) * STAGE_B;
#pragma unroll
        for (int v = 0; v < 6; ++v) {
            int idx = v * 256 + tid;
            int arr = idx >> 9;          // 0..2
            int r   = (idx >> 2) & 127;
            int c   = idx & 3;
            int grow = (arr < 2 ? m0 : n0) + r;
            const __half* gp = gsrc[arr] + (size_t)grow * Kd + kt + c * 8;
            cp_async16(sb + arr * ARR_B + r * ROWB + c * 16, gp);
        }
    };

    load_stage(0);
    CP_COMMIT();

    for (int s = 0; s < NS; ++s) {
        if (s + 1 < NS) { load_stage(s + 1); CP_COMMIT(); CP_WAIT(1); }
        else            { CP_WAIT(0); }
        __syncthreads();

        const uint32_t sb = sbase + (s & 1) * STAGE_B;
        const uint32_t aHb = sb + (mw + (lane & 15)) * ROWB + (lane >> 4) * 16;
        const uint32_t aLb = aHb + ARR_B;
        const uint32_t bRow = nw + ((lane >> 4) << 3) + (lane & 7);
        const uint32_t bHb = sb + 2 * ARR_B + bRow * ROWB + ((lane >> 3) & 1) * 16;

#pragma unroll
        for (int kk = 0; kk < 2; ++kk) {
            const uint32_t ko = kk * 32;       // 16 halves = 32B
            uint32_t ah[2][4], al[2][4];
            ldsm_x4(ah[0][0], ah[0][1], ah[0][2], ah[0][3], aHb + ko);
            ldsm_x4(ah[1][0], ah[1][1], ah[1][2], ah[1][3], aHb + 16 * ROWB + ko);
            ldsm_x4(al[0][0], al[0][1], al[0][2], al[0][3], aLb + ko);
            ldsm_x4(al[1][0], al[1][1], al[1][2], al[1][3], aLb + 16 * ROWB + ko);

            uint32_t bh[8][2];
#pragma unroll
            for (int g = 0; g < 4; ++g)
                ldsm_x4(bh[2*g][0], bh[2*g][1], bh[2*g+1][0], bh[2*g+1][1],
                        bHb + g * 16 * ROWB + ko);
#pragma unroll
            for (int mt = 0; mt < 2; ++mt)
#pragma unroll
                for (int n8 = 0; n8 < 8; ++n8)
                    mma_f16(acc[mt][n8], ah[mt], bh[n8]);   // hi*hi
#pragma unroll
            for (int mt = 0; mt < 2; ++mt)
#pragma unroll
                for (int n8 = 0; n8 < 8; ++n8)
                    mma_f16(acc[mt][n8], al[mt], bh[n8]);   // lo*hi
        }
        __syncthreads();
    }

    // Epilogue
#pragma unroll
    for (int mt = 0; mt < 2; ++mt) {
        const int row = m0 + mw + mt * 16 + (lane >> 2);
        const int col = n0 + nw + (lane & 3) * 2;
        if (SPLIT_OUT) {
            __half* h0 = Ch + (size_t)row * ldc + col;
            __half* h1 = Ch + (size_t)(row + 8) * ldc + col;
            __half* l0 = Cl + (size_t)row * ldc + col;
            __half* l1 = Cl + (size_t)(row + 8) * ldc + col;
#pragma unroll
            for (int n8 = 0; n8 < 8; ++n8) {
                uint32_t hh, ll;
                split2h(acc[mt][n8][0], acc[mt][n8][1], hh, ll);
                *(uint32_t*)(h0 + n8 * 8) = hh;
                *(uint32_t*)(l0 + n8 * 8) = ll;
                split2h(acc[mt][n8][2], acc[mt][n8][3], hh, ll);
                *(uint32_t*)(h1 + n8 * 8) = hh;
                *(uint32_t*)(l1 + n8 * 8) = ll;
            }
        } else {
            float* c0 = C + (size_t)row * ldc + col;
            float* c1 = C + (size_t)(row + 8) * ldc + col;
#pragma unroll
            for (int n8 = 0; n8 < 8; ++n8) {
                *(float2*)(c0 + n8 * 8) = make_float2(acc[mt][n8][0], acc[mt][n8][1]);
                *(float2*)(c1 + n8 * 8) = make_float2(acc[mt][n8][2], acc[mt][n8][3]);
            }
        }
    }
}

// ---------------------------------------------------------------------------
// Tensor-core flash attention (causal, multi-query, 2-pass fp16 split).
// Q tile 128x64 per CTA, 8 warps x 16 rows; K/V hi tiles 64x64 double-buffered.
// S = (Qh+Ql)*Kh ; O += (Ph+Pl)*Vh. Softmax register-resident.
// ---------------------------------------------------------------------------
#define FT_ROWB 144
#define FT_ARR  (64 * FT_ROWB)      // 9216 B
#define FT_STG  (2 * FT_ARR)        // Kh, Vh = 18432 B
#define FT_SMEM (2 * FT_STG)        // 36864 B

__global__ __launch_bounds__(256) void flash_tc(
    const __half* __restrict__ QKVh,
    const __half* __restrict__ QKVl,
    __half* __restrict__ Yh, __half* __restrict__ Yl)
{
    extern __shared__ __align__(16) char smd[];
    const uint32_t sbase = smem_u32(smd);
    const int tid = threadIdx.x, lane = tid & 31, wid = tid >> 5;
    const int h = blockIdx.y, b = blockIdx.z;
    const int qb = (int)gridDim.x - 1 - (int)blockIdx.x;   // longest first
    const int i0 = qb * 128;
    const int g = lane >> 2, qd = lane & 3;

    uint32_t qh[4][4], ql[4][4];
    {
        const int r0 = i0 + wid * 16 + g;
        const size_t b0 = (size_t)(b * TT + r0) * NQKV + h * 64;
        const size_t b1 = b0 + (size_t)8 * NQKV;
#pragma unroll
        for (int t = 0; t < 4; ++t) {
            const int c = t * 16 + qd * 2;
            qh[t][0] = *(const uint32_t*)(QKVh + b0 + c);
            qh[t][1] = *(const uint32_t*)(QKVh + b1 + c);
            qh[t][2] = *(const uint32_t*)(QKVh + b0 + c + 8);
            qh[t][3] = *(const uint32_t*)(QKVh + b1 + c + 8);
            ql[t][0] = *(const uint32_t*)(QKVl + b0 + c);
            ql[t][1] = *(const uint32_t*)(QKVl + b1 + c);
            ql[t][2] = *(const uint32_t*)(QKVl + b0 + c + 8);
            ql[t][3] = *(const uint32_t*)(QKVl + b1 + c + 8);
        }
    }

    float o[8][4];
#pragma unroll
    for (int n8 = 0; n8 < 8; ++n8)
#pragma unroll
        for (int c = 0; c < 4; ++c) o[n8][c] = 0.f;
    float m0 = -1e30f, m1 = -1e30f, l0 = 0.f, l1 = 0.f;

    // --- K/V hi stage loader: 1024 x 16B chunks, 4 per thread ---
    auto load_kv = [&](int it) {
        const int j0 = it * 64;
        const uint32_t sb = sbase + (it & 1) * FT_STG;
#pragma unroll
        for (int v = 0; v < 4; ++v) {
            int idx = v * 256 + tid;
            int arr = idx >> 9, r = (idx >> 3) & 63, c = idx & 7;   // arr: 0=K,1=V
            int col = (arr == 0 ? 1024 : 1088) + c * 8;
            cp_async16(sb + arr * FT_ARR + r * FT_ROWB + c * 16,
                       QKVh + (size_t)(b * TT + j0 + r) * NQKV + col);
        }
    };

    load_kv(0);
    CP_COMMIT();

    const int nIter = 2 * qb + 2;
    for (int it = 0; it < nIter; ++it) {
        if (it + 1 < nIter) { load_kv(it + 1); CP_COMMIT(); CP_WAIT(1); }
        else                { CP_WAIT(0); }
        __syncthreads();

        const uint32_t sb = sbase + (it & 1) * FT_STG;

        // ---- S = (Qh+Ql) Kh^T ----
        float s[8][4];
#pragma unroll
        for (int n8 = 0; n8 < 8; ++n8)
#pragma unroll
            for (int c = 0; c < 4; ++c) s[n8][c] = 0.f;

        const uint32_t kA = sb + (((lane >> 4) << 3) + (lane & 7)) * FT_ROWB
                          + ((lane >> 3) & 1) * 16;
#pragma unroll
        for (int t = 0; t < 4; ++t) {
            uint32_t kh[8][2];
#pragma unroll
            for (int gg = 0; gg < 4; ++gg)
                ldsm_x4(kh[2*gg][0], kh[2*gg][1], kh[2*gg+1][0], kh[2*gg+1][1],
                        kA + gg * 16 * FT_ROWB + t * 32);
#pragma unroll
            for (int n8 = 0; n8 < 8; ++n8) mma_f16(s[n8], qh[t], kh[n8]);
#pragma unroll
            for (int n8 = 0; n8 < 8; ++n8) mma_f16(s[n8], ql[t], kh[n8]);
        }

        // ---- scale + causal mask ----
        const int j0 = it * 64;
        const int r0 = i0 + wid * 16 + g;
        const bool msk = (j0 + 63 > i0 + wid * 16);
#pragma unroll
        for (int n8 = 0; n8 < 8; ++n8) {
#pragma unroll
            for (int c = 0; c < 4; ++c) s[n8][c] *= 0.125f;
            if (msk) {
                const int j = j0 + n8 * 8 + qd * 2;
                if (j     > r0)     s[n8][0] = -1e30f;
                if (j + 1 > r0)     s[n8][1] = -1e30f;
                if (j     > r0 + 8) s[n8][2] = -1e30f;
                if (j + 1 > r0 + 8) s[n8][3] = -1e30f;
            }
        }

        // ---- online softmax (register-resident) ----
        float mx0 = -1e30f, mx1 = -1e30f;
#pragma unroll
        for (int n8 = 0; n8 < 8; ++n8) {
            mx0 = fmaxf(mx0, fmaxf(s[n8][0], s[n8][1]));
            mx1 = fmaxf(mx1, fmaxf(s[n8][2], s[n8][3]));
        }
        mx0 = fmaxf(mx0, __shfl_xor_sync(0xffffffffu, mx0, 1));
        mx0 = fmaxf(mx0, __shfl_xor_sync(0xffffffffu, mx0, 2));
        mx1 = fmaxf(mx1, __shfl_xor_sync(0xffffffffu, mx1, 1));
        mx1 = fmaxf(mx1, __shfl_xor_sync(0xffffffffu, mx1, 2));
        const float mn0 = fmaxf(m0, mx0), mn1 = fmaxf(m1, mx1);
        const float sc0 = __expf(m0 - mn0), sc1 = __expf(m1 - mn1);
        m0 = mn0; m1 = mn1;

        float sum0 = 0.f, sum1 = 0.f;
        uint32_t ph[4][4], pl[4][4];
#pragma unroll
        for (int t = 0; t < 4; ++t) {
            float p00 = __expf(s[2*t][0] - mn0),   p01 = __expf(s[2*t][1] - mn0);
            float p02 = __expf(s[2*t][2] - mn1),   p03 = __expf(s[2*t][3] - mn1);
            float p10 = __expf(s[2*t+1][0] - mn0), p11 = __expf(s[2*t+1][1] - mn0);
            float p12 = __expf(s[2*t+1][2] - mn1), p13 = __expf(s[2*t+1][3] - mn1);
            sum0 += p00 + p01 + p10 + p11;
            sum1 += p02 + p03 + p12 + p13;
            split2h(p00, p01, ph[t][0], pl[t][0]);
            split2h(p02, p03, ph[t][1], pl[t][1]);
            split2h(p10, p11, ph[t][2], pl[t][2]);
            split2h(p12, p13, ph[t][3], pl[t][3]);
        }
        sum0 += __shfl_xor_sync(0xffffffffu, sum0, 1);
        sum0 += __shfl_xor_sync(0xffffffffu, sum0, 2);
        sum1 += __shfl_xor_sync(0xffffffffu, sum1, 1);
        sum1 += __shfl_xor_sync(0xffffffffu, sum1, 2);
        l0 = l0 * sc0 + sum0;
        l1 = l1 * sc1 + sum1;
#pragma unroll
        for (int n8 = 0; n8 < 8; ++n8) {
            o[n8][0] *= sc0; o[n8][1] *= sc0;
            o[n8][2] *= sc1; o[n8][3] *= sc1;
        }

        // ---- O += (Ph+Pl) Vh ----
        const uint32_t vA = sb + FT_ARR
                          + ((lane & 7) + ((lane >> 3) & 1) * 8) * FT_ROWB
                          + (lane >> 4) * 16;
#pragma unroll
        for (int t = 0; t < 4; ++t) {
            uint32_t vh[8][2];
#pragma unroll
            for (int dg = 0; dg < 4; ++dg)
                ldsm_x4_t(vh[2*dg][0], vh[2*dg][1], vh[2*dg+1][0], vh[2*dg+1][1],
                          vA + t * 16 * FT_ROWB + dg * 32);
#pragma unroll
            for (int n8 = 0; n8 < 8; ++n8) mma_f16(o[n8], ph[t], vh[n8]);
#pragma unroll
            for (int n8 = 0; n8 < 8; ++n8) mma_f16(o[n8], pl[t], vh[n8]);
        }
        __syncthreads();
    }

    // ---- epilogue: normalize and write Y as fp16 hi/lo (fused split) ----
    const float inv0 = 1.f / l0, inv1 = 1.f / l1;
    const int r0 = i0 + wid * 16 + g;
    const size_t off0 = (size_t)(b * TT + r0) * DD + h * 64 + qd * 2;
    const size_t off1 = off0 + (size_t)8 * DD;
#pragma unroll
    for (int n8 = 0; n8 < 8; ++n8) {
        uint32_t hh, ll;
        split2h(o[n8][0] * inv0, o[n8][1] * inv0, hh, ll);
        *(uint32_t*)(Yh + off0 + n8 * 8) = hh;
        *(uint32_t*)(Yl + off0 + n8 * 8) = ll;
        split2h(o[n8][2] * inv1, o[n8][3] * inv1, hh, ll);
        *(uint32_t*)(Yh + off1 + n8 * 8) = hh;
        *(uint32_t*)(Yl + off1 + n8 * 8) = ll;
    }
}

// ---------------------------------------------------------------------------
extern "C" void kernel_launch(void* const* d_in, const int* in_sizes, int n_in,
                              void* d_out, int out_size)
{
    (void)in_sizes; (void)n_in; (void)out_size;
    const float* x  = (const float*)d_in[0];
    const float* Wq = (const float*)d_in[1];
    const float* Wk = (const float*)d_in[2];
    const float* Wv = (const float*)d_in[3];
    const float* Wo = (const float*)d_in[4];
    float* out = (float*)d_out;

    unsigned short *qkvh, *qkvl, *xh, *xl, *Bh, *Yh, *Yl, *Woh;
    cudaGetSymbolAddress((void**)&qkvh, g_QKVh);
    cudaGetSymbolAddress((void**)&qkvl, g_QKVl);
    cudaGetSymbolAddress((void**)&xh, g_xhi);
    cudaGetSymbolAddress((void**)&xl, g_xlo);
    cudaGetSymbolAddress((void**)&Bh, g_Bhi);
    cudaGetSymbolAddress((void**)&Yh, g_Yhi);
    cudaGetSymbolAddress((void**)&Yl, g_Ylo);
    cudaGetSymbolAddress((void**)&Woh, g_Wohi);

    cudaFuncSetAttribute(gemm_split_mma<true>,
                         cudaFuncAttributeMaxDynamicSharedMemorySize, GEMM_SMEM_BYTES);
    cudaFuncSetAttribute(gemm_split_mma<false>,
                         cudaFuncAttributeMaxDynamicSharedMemorySize, GEMM_SMEM_BYTES);
    cudaFuncSetAttribute(flash_tc,
                         cudaFuncAttributeMaxDynamicSharedMemorySize, FT_SMEM);

    const int n4x = MTOT * DD / 4;

    // 1) Split x -> fp16 hi/lo
    conv_split<<<n4x / 256, 256>>>((const float4*)x,
        (__half2*)xh, (__half2*)xl, n4x);

    // 2) Transpose+round weights to fp16 hi: fused B [N=1152, K=1024] + Wo^T
    convT_h<<<dim3(32, 32), 256>>>(Wq, 1024, (__half*)Bh, 0);
    convT_h<<<dim3(2, 32),  256>>>(Wk, 64,   (__half*)Bh, 1024);
    convT_h<<<dim3(2, 32),  256>>>(Wv, 64,   (__half*)Bh, 1088);
    convT_h<<<dim3(32, 32), 256>>>(Wo, 1024, (__half*)Woh, 0);

    // 3) Fused QKV projection, epilogue emits fp16 hi/lo directly
    gemm_split_mma<true><<<dim3(NQKV / 128, MTOT / 128), 256, GEMM_SMEM_BYTES>>>(
        (const __half*)xh, (const __half*)xl, (const __half*)Bh,
        nullptr, (__half*)qkvh, (__half*)qkvl, DD, NQKV);

    // 4) Tensor-core causal multi-query flash attention -> Yh/Yl (fused split)
    flash_tc<<<dim3(TT / 128, HH, BB), 256, FT_SMEM>>>(
        (const __half*)qkvh, (const __half*)qkvl,
        (__half*)Yh, (__half*)Yl);

    // 5) Output projection: out = Y @ Wo (fp32 epilogue)
    gemm_split_mma<false><<<dim3(DD / 128, MTOT / 128), 256, GEMM_SMEM_BYTES>>>(
        (const __half*)Yh, (const __half*)Yl, (const __half*)Woh,
        out, nullptr, nullptr, DD, DD);
}

// round 10
// speedup vs baseline: 1.7863x; 1.2738x over previous
#include <cuda_runtime.h>
#include <cuda_fp16.h>
#include <cstdint>

// Problem shapes (fixed by the dataset).
#define BB 2
#define TT 2048
#define DD 1024
#define HH 16
#define DKK 64
#define MTOT (BB*TT)     // 4096 rows
#define NQKV 1152        // fused projection width: 1024 Q + 64 K + 64 V

// softmax scale folded with log2(e): 0.125 * 1.4426950408889634
#define SM_SCALE 0.18033688011112042f

// ---------------------------------------------------------------------------
// Device scratch (allocation-free per harness rules).  All fp16.
// ---------------------------------------------------------------------------
__device__ unsigned short g_QKVh[MTOT * NQKV], g_QKVl[MTOT * NQKV]; // QKV fp16 hi/lo
__device__ unsigned short g_xhi[MTOT * DD], g_xlo[MTOT * DD];    // x fp16 hi/lo
__device__ unsigned short g_Bhi[NQKV * DD];                      // [Wq;Wk;Wv]^T fp16 hi
__device__ unsigned short g_Yhi[MTOT * DD];                      // Y fp16 hi
__device__ unsigned short g_Wohi[DD * DD];                       // Wo^T fp16 hi

// ---------------------------------------------------------------------------
// Generic-PTX tensor helpers (NO arch-'a' features: work on plain sm_103).
// ---------------------------------------------------------------------------
__device__ __forceinline__ uint32_t smem_u32(const void* p) {
    uint32_t a;
    asm("{ .reg .u64 t; cvta.to.shared.u64 t, %1; cvt.u32.u64 %0, t; }"
        : "=r"(a) : "l"(p));
    return a;
}

__device__ __forceinline__ void ldsm_x4(uint32_t& r0, uint32_t& r1,
                                        uint32_t& r2, uint32_t& r3, uint32_t a) {
    asm volatile("ldmatrix.sync.aligned.m8n8.x4.shared.b16 {%0,%1,%2,%3}, [%4];"
                 : "=r"(r0), "=r"(r1), "=r"(r2), "=r"(r3) : "r"(a));
}
__device__ __forceinline__ void ldsm_x4_t(uint32_t& r0, uint32_t& r1,
                                          uint32_t& r2, uint32_t& r3, uint32_t a) {
    asm volatile("ldmatrix.sync.aligned.m8n8.x4.trans.shared.b16 {%0,%1,%2,%3}, [%4];"
                 : "=r"(r0), "=r"(r1), "=r"(r2), "=r"(r3) : "r"(a));
}

// fp16 tensor-core MMA, fp32 accumulate.
__device__ __forceinline__ void mma_f16(float* d, const uint32_t* a,
                                        const uint32_t* b) {
    asm volatile(
        "mma.sync.aligned.m16n8k16.row.col.f32.f16.f16.f32 "
        "{%0,%1,%2,%3}, {%4,%5,%6,%7}, {%8,%9}, {%0,%1,%2,%3};"
        : "+f"(d[0]), "+f"(d[1]), "+f"(d[2]), "+f"(d[3])
        : "r"(a[0]), "r"(a[1]), "r"(a[2]), "r"(a[3]), "r"(b[0]), "r"(b[1]));
}

__device__ __forceinline__ void cp_async16(uint32_t saddr, const void* g) {
    asm volatile("cp.async.cg.shared.global [%0], [%1], 16;" :: "r"(saddr), "l"(g));
}
#define CP_COMMIT() asm volatile("cp.async.commit_group;" ::: "memory")
#define CP_WAIT(n)  asm volatile("cp.async.wait_group %0;" :: "n"(n) : "memory")

// Fast 2^x (single MUFU op).
__device__ __forceinline__ float ex2(float x) {
    float r;
    asm("ex2.approx.ftz.f32 %0, %1;" : "=f"(r) : "f"(x));
    return r;
}

// Split two fp32 into packed fp16x2 hi & lo parts (low half = first element).
__device__ __forceinline__ void split2h(float a, float b, uint32_t& hi, uint32_t& lo) {
    __half ha = __float2half(a), hb = __float2half(b);
    __half la = __float2half(a - __half2float(ha));
    __half lb = __float2half(b - __half2float(hb));
    __half2 H = __halves2half2(ha, hb);
    __half2 L = __halves2half2(la, lb);
    hi = *reinterpret_cast<uint32_t*>(&H);
    lo = *reinterpret_cast<uint32_t*>(&L);
}
// Round two fp32 to a packed fp16x2.
__device__ __forceinline__ uint32_t pack2h(float a, float b) {
    __half2 H = __floats2half2_rn(a, b);
    return *reinterpret_cast<uint32_t*>(&H);
}

// ---------------------------------------------------------------------------
// Conversion kernels.
// ---------------------------------------------------------------------------
__global__ __launch_bounds__(256) void conv_split(
    const float4* __restrict__ a, __half2* __restrict__ hi,
    __half2* __restrict__ lo, int n4)
{
    int i = blockIdx.x * blockDim.x + threadIdx.x;
    if (i >= n4) return;
    float4 v = a[i];
    uint32_t h0, l0, h1, l1;
    split2h(v.x, v.y, h0, l0);
    split2h(v.z, v.w, h1, l1);
    ((uint32_t*)hi)[2*i]   = h0;
    ((uint32_t*)hi)[2*i+1] = h1;
    ((uint32_t*)lo)[2*i]   = l0;
    ((uint32_t*)lo)[2*i+1] = l1;
}

// Transpose + round: W[K=1024, N] row-major -> oh[(n_off+n)*1024 + k] fp16 (hi only).
__global__ __launch_bounds__(256) void convT_h(
    const float* __restrict__ W, int N,
    __half* __restrict__ oh, int n_off)
{
    __shared__ float t[32][33];
    const int k0 = blockIdx.y * 32, n0 = blockIdx.x * 32;
    const int tx = threadIdx.x & 31, ty = threadIdx.x >> 5;  // 32 x 8
#pragma unroll
    for (int j = 0; j < 4; ++j)
        t[ty + 8*j][tx] = W[(size_t)(k0 + ty + 8*j) * N + n0 + tx];
    __syncthreads();
#pragma unroll
    for (int j = 0; j < 4; ++j) {
        float v = t[tx][ty + 8*j];   // = W[k0+tx][n0+ty+8j]
        oh[(size_t)(n_off + n0 + ty + 8*j) * 1024 + k0 + tx] = __float2half(v);
    }
}

// ---------------------------------------------------------------------------
// fp16 split GEMM via mma.sync: C = (Ah [+ Al]) * Bh^T.
// CTA tile 128x128, 8 warps (each 32x64), K-stage 32, cp.async double buffer.
// TWO_A: include the Al*Bh correction pass. SPLIT_OUT: emit fp16 hi/lo.
// ---------------------------------------------------------------------------
#define ROWB 80                 // 32 fp16 = 64B data + 16B pad
#define ARR_B (128 * ROWB)      // 10240 B

template<bool SPLIT_OUT, bool TWO_A>
__global__ __launch_bounds__(256, 2) void gemm_split_mma(
    const __half* __restrict__ Ah, const __half* __restrict__ Al,
    const __half* __restrict__ Bh,
    float* __restrict__ C, __half* __restrict__ Ch,
    __half* __restrict__ Cl, int Kd, int ldc)
{
    constexpr int NARR = TWO_A ? 3 : 2;
    constexpr int STAGE_B = NARR * ARR_B;
    extern __shared__ __align__(16) char smd[];
    const uint32_t sbase = smem_u32(smd);
    const int tid  = threadIdx.x;
    const int lane = tid & 31;
    const int w    = tid >> 5;
    const int m0 = blockIdx.y * 128;
    const int n0 = blockIdx.x * 128;
    const int mw = (w >> 1) * 32;
    const int nw = (w & 1) * 64;

    float acc[2][8][4];
#pragma unroll
    for (int mt = 0; mt < 2; ++mt)
#pragma unroll
        for (int n8 = 0; n8 < 8; ++n8)
#pragma unroll
            for (int q = 0; q < 4; ++q) acc[mt][n8][q] = 0.f;

    const int NS = Kd >> 5;   // K-stages of 32

    // --- stage loader: NARR*512 x 16B chunks, 2*NARR per thread ---
    auto load_stage = [&](int s) {
        const int kt = s << 5;
        const uint32_t sb = sbase + (s & 1) * STAGE_B;
#pragma unroll
        for (int v = 0; v < 2 * NARR; ++v) {
            int idx = v * 256 + tid;
            int arr = idx >> 9;          // 0..NARR-1
            int r   = (idx >> 2) & 127;
            int c   = idx & 3;
            const __half* base = (arr == NARR - 1) ? Bh : (arr == 0 ? Ah : Al);
            int grow = (arr == NARR - 1 ? n0 : m0) + r;
            cp_async16(sb + arr * ARR_B + r * ROWB + c * 16,
                       base + (size_t)grow * Kd + kt + c * 8);
        }
    };

    load_stage(0);
    CP_COMMIT();

    for (int s = 0; s < NS; ++s) {
        if (s + 1 < NS) { load_stage(s + 1); CP_COMMIT(); CP_WAIT(1); }
        else            { CP_WAIT(0); }
        __syncthreads();

        const uint32_t sb = sbase + (s & 1) * STAGE_B;
        const uint32_t aHb = sb + (mw + (lane & 15)) * ROWB + (lane >> 4) * 16;
        const uint32_t aLb = aHb + ARR_B;
        const uint32_t bRow = nw + ((lane >> 4) << 3) + (lane & 7);
        const uint32_t bHb = sb + (NARR - 1) * ARR_B + bRow * ROWB
                           + ((lane >> 3) & 1) * 16;

#pragma unroll
        for (int kk = 0; kk < 2; ++kk) {
            const uint32_t ko = kk * 32;       // 16 halves = 32B
            uint32_t ah[2][4];
            ldsm_x4(ah[0][0], ah[0][1], ah[0][2], ah[0][3], aHb + ko);
            ldsm_x4(ah[1][0], ah[1][1], ah[1][2], ah[1][3], aHb + 16 * ROWB + ko);

            uint32_t bh[8][2];
#pragma unroll
            for (int g = 0; g < 4; ++g)
                ldsm_x4(bh[2*g][0], bh[2*g][1], bh[2*g+1][0], bh[2*g+1][1],
                        bHb + g * 16 * ROWB + ko);
#pragma unroll
            for (int mt = 0; mt < 2; ++mt)
#pragma unroll
                for (int n8 = 0; n8 < 8; ++n8)
                    mma_f16(acc[mt][n8], ah[mt], bh[n8]);   // hi*hi

            if (TWO_A) {
                uint32_t al[2][4];
                ldsm_x4(al[0][0], al[0][1], al[0][2], al[0][3], aLb + ko);
                ldsm_x4(al[1][0], al[1][1], al[1][2], al[1][3], aLb + 16 * ROWB + ko);
#pragma unroll
                for (int mt = 0; mt < 2; ++mt)
#pragma unroll
                    for (int n8 = 0; n8 < 8; ++n8)
                        mma_f16(acc[mt][n8], al[mt], bh[n8]);   // lo*hi
            }
        }
        __syncthreads();
    }

    // Epilogue
#pragma unroll
    for (int mt = 0; mt < 2; ++mt) {
        const int row = m0 + mw + mt * 16 + (lane >> 2);
        const int col = n0 + nw + (lane & 3) * 2;
        if (SPLIT_OUT) {
            __half* h0 = Ch + (size_t)row * ldc + col;
            __half* h1 = Ch + (size_t)(row + 8) * ldc + col;
            __half* l0 = Cl + (size_t)row * ldc + col;
            __half* l1 = Cl + (size_t)(row + 8) * ldc + col;
#pragma unroll
            for (int n8 = 0; n8 < 8; ++n8) {
                uint32_t hh, ll;
                split2h(acc[mt][n8][0], acc[mt][n8][1], hh, ll);
                *(uint32_t*)(h0 + n8 * 8) = hh;
                *(uint32_t*)(l0 + n8 * 8) = ll;
                split2h(acc[mt][n8][2], acc[mt][n8][3], hh, ll);
                *(uint32_t*)(h1 + n8 * 8) = hh;
                *(uint32_t*)(l1 + n8 * 8) = ll;
            }
        } else {
            float* c0 = C + (size_t)row * ldc + col;
            float* c1 = C + (size_t)(row + 8) * ldc + col;
#pragma unroll
            for (int n8 = 0; n8 < 8; ++n8) {
                *(float2*)(c0 + n8 * 8) = make_float2(acc[mt][n8][0], acc[mt][n8][1]);
                *(float2*)(c1 + n8 * 8) = make_float2(acc[mt][n8][2], acc[mt][n8][3]);
            }
        }
    }
}

#define GEMM_SMEM_2A (2 * 3 * ARR_B)   // 61440 B
#define GEMM_SMEM_1A (2 * 2 * ARR_B)   // 40960 B

// ---------------------------------------------------------------------------
// Tensor-core flash attention (causal, multi-query).
// S = (Qh+Ql)*Kh (2-pass); P rounded to fp16, O += Ph*Vh (1-pass).
// Q tile 128x64 per CTA, 8 warps x 16 rows; softmax register-resident,
// exp in base-2 domain (scale folded with log2 e). Y emitted fp16 hi only.
// ---------------------------------------------------------------------------
#define FT_ROWB 144
#define FT_ARR  (64 * FT_ROWB)      // 9216 B
#define FT_STG  (2 * FT_ARR)        // Kh, Vh = 18432 B
#define FT_SMEM (2 * FT_STG)        // 36864 B

__global__ __launch_bounds__(256) void flash_tc(
    const __half* __restrict__ QKVh,
    const __half* __restrict__ QKVl,
    __half* __restrict__ Yh)
{
    extern __shared__ __align__(16) char smd[];
    const uint32_t sbase = smem_u32(smd);
    const int tid = threadIdx.x, lane = tid & 31, wid = tid >> 5;
    const int h = blockIdx.y, b = blockIdx.z;
    const int qb = (int)gridDim.x - 1 - (int)blockIdx.x;   // longest first
    const int i0 = qb * 128;
    const int g = lane >> 2, qd = lane & 3;

    uint32_t qh[4][4], ql[4][4];
    {
        const int r0 = i0 + wid * 16 + g;
        const size_t b0 = (size_t)(b * TT + r0) * NQKV + h * 64;
        const size_t b1 = b0 + (size_t)8 * NQKV;
#pragma unroll
        for (int t = 0; t < 4; ++t) {
            const int c = t * 16 + qd * 2;
            qh[t][0] = *(const uint32_t*)(QKVh + b0 + c);
            qh[t][1] = *(const uint32_t*)(QKVh + b1 + c);
            qh[t][2] = *(const uint32_t*)(QKVh + b0 + c + 8);
            qh[t][3] = *(const uint32_t*)(QKVh + b1 + c + 8);
            ql[t][0] = *(const uint32_t*)(QKVl + b0 + c);
            ql[t][1] = *(const uint32_t*)(QKVl + b1 + c);
            ql[t][2] = *(const uint32_t*)(QKVl + b0 + c + 8);
            ql[t][3] = *(const uint32_t*)(QKVl + b1 + c + 8);
        }
    }

    float o[8][4];
#pragma unroll
    for (int n8 = 0; n8 < 8; ++n8)
#pragma unroll
        for (int c = 0; c < 4; ++c) o[n8][c] = 0.f;
    float m0 = -1e30f, m1 = -1e30f, l0 = 0.f, l1 = 0.f;

    // --- K/V hi stage loader: 1024 x 16B chunks, 4 per thread ---
    auto load_kv = [&](int it) {
        const int j0 = it * 64;
        const uint32_t sb = sbase + (it & 1) * FT_STG;
#pragma unroll
        for (int v = 0; v < 4; ++v) {
            int idx = v * 256 + tid;
            int arr = idx >> 9, r = (idx >> 3) & 63, c = idx & 7;   // arr: 0=K,1=V
            int col = (arr == 0 ? 1024 : 1088) + c * 8;
            cp_async16(sb + arr * FT_ARR + r * FT_ROWB + c * 16,
                       QKVh + (size_t)(b * TT + j0 + r) * NQKV + col);
        }
    };

    load_kv(0);
    CP_COMMIT();

    const int nIter = 2 * qb + 2;
    for (int it = 0; it < nIter; ++it) {
        if (it + 1 < nIter) { load_kv(it + 1); CP_COMMIT(); CP_WAIT(1); }
        else                { CP_WAIT(0); }
        __syncthreads();

        const uint32_t sb = sbase + (it & 1) * FT_STG;

        // ---- S = (Qh+Ql) Kh^T ----
        float s[8][4];
#pragma unroll
        for (int n8 = 0; n8 < 8; ++n8)
#pragma unroll
            for (int c = 0; c < 4; ++c) s[n8][c] = 0.f;

        const uint32_t kA = sb + (((lane >> 4) << 3) + (lane & 7)) * FT_ROWB
                          + ((lane >> 3) & 1) * 16;
#pragma unroll
        for (int t = 0; t < 4; ++t) {
            uint32_t kh[8][2];
#pragma unroll
            for (int gg = 0; gg < 4; ++gg)
                ldsm_x4(kh[2*gg][0], kh[2*gg][1], kh[2*gg+1][0], kh[2*gg+1][1],
                        kA + gg * 16 * FT_ROWB + t * 32);
#pragma unroll
            for (int n8 = 0; n8 < 8; ++n8) mma_f16(s[n8], qh[t], kh[n8]);
#pragma unroll
            for (int n8 = 0; n8 < 8; ++n8) mma_f16(s[n8], ql[t], kh[n8]);
        }

        // ---- scale (base-2 domain) + causal mask ----
        const int j0 = it * 64;
        const int r0 = i0 + wid * 16 + g;
        const bool msk = (j0 + 63 > i0 + wid * 16);
#pragma unroll
        for (int n8 = 0; n8 < 8; ++n8) {
#pragma unroll
            for (int c = 0; c < 4; ++c) s[n8][c] *= SM_SCALE;
            if (msk) {
                const int j = j0 + n8 * 8 + qd * 2;
                if (j     > r0)     s[n8][0] = -1e30f;
                if (j + 1 > r0)     s[n8][1] = -1e30f;
                if (j     > r0 + 8) s[n8][2] = -1e30f;
                if (j + 1 > r0 + 8) s[n8][3] = -1e30f;
            }
        }

        // ---- online softmax (register-resident, base-2 exp) ----
        float mx0 = -1e30f, mx1 = -1e30f;
#pragma unroll
        for (int n8 = 0; n8 < 8; ++n8) {
            mx0 = fmaxf(mx0, fmaxf(s[n8][0], s[n8][1]));
            mx1 = fmaxf(mx1, fmaxf(s[n8][2], s[n8][3]));
        }
        mx0 = fmaxf(mx0, __shfl_xor_sync(0xffffffffu, mx0, 1));
        mx0 = fmaxf(mx0, __shfl_xor_sync(0xffffffffu, mx0, 2));
        mx1 = fmaxf(mx1, __shfl_xor_sync(0xffffffffu, mx1, 1));
        mx1 = fmaxf(mx1, __shfl_xor_sync(0xffffffffu, mx1, 2));
        const float mn0 = fmaxf(m0, mx0), mn1 = fmaxf(m1, mx1);
        const float sc0 = ex2(m0 - mn0), sc1 = ex2(m1 - mn1);
        m0 = mn0; m1 = mn1;

        float sum0 = 0.f, sum1 = 0.f;
        uint32_t ph[4][4];
#pragma unroll
        for (int t = 0; t < 4; ++t) {
            float p00 = ex2(s[2*t][0] - mn0),   p01 = ex2(s[2*t][1] - mn0);
            float p02 = ex2(s[2*t][2] - mn1),   p03 = ex2(s[2*t][3] - mn1);
            float p10 = ex2(s[2*t+1][0] - mn0), p11 = ex2(s[2*t+1][1] - mn0);
            float p12 = ex2(s[2*t+1][2] - mn1), p13 = ex2(s[2*t+1][3] - mn1);
            sum0 += p00 + p01 + p10 + p11;
            sum1 += p02 + p03 + p12 + p13;
            ph[t][0] = pack2h(p00, p01);
            ph[t][1] = pack2h(p02, p03);
            ph[t][2] = pack2h(p10, p11);
            ph[t][3] = pack2h(p12, p13);
        }
        sum0 += __shfl_xor_sync(0xffffffffu, sum0, 1);
        sum0 += __shfl_xor_sync(0xffffffffu, sum0, 2);
        sum1 += __shfl_xor_sync(0xffffffffu, sum1, 1);
        sum1 += __shfl_xor_sync(0xffffffffu, sum1, 2);
        l0 = l0 * sc0 + sum0;
        l1 = l1 * sc1 + sum1;
#pragma unroll
        for (int n8 = 0; n8 < 8; ++n8) {
            o[n8][0] *= sc0; o[n8][1] *= sc0;
            o[n8][2] *= sc1; o[n8][3] *= sc1;
        }

        // ---- O += Ph Vh (single pass) ----
        const uint32_t vA = sb + FT_ARR
                          + ((lane & 7) + ((lane >> 3) & 1) * 8) * FT_ROWB
                          + (lane >> 4) * 16;
#pragma unroll
        for (int t = 0; t < 4; ++t) {
            uint32_t vh[8][2];
#pragma unroll
            for (int dg = 0; dg < 4; ++dg)
                ldsm_x4_t(vh[2*dg][0], vh[2*dg][1], vh[2*dg+1][0], vh[2*dg+1][1],
                          vA + t * 16 * FT_ROWB + dg * 32);
#pragma unroll
            for (int n8 = 0; n8 < 8; ++n8) mma_f16(o[n8], ph[t], vh[n8]);
        }
        __syncthreads();
    }

    // ---- epilogue: normalize and write Y as fp16 hi only ----
    const float inv0 = 1.f / l0, inv1 = 1.f / l1;
    const int r0 = i0 + wid * 16 + g;
    const size_t off0 = (size_t)(b * TT + r0) * DD + h * 64 + qd * 2;
    const size_t off1 = off0 + (size_t)8 * DD;
#pragma unroll
    for (int n8 = 0; n8 < 8; ++n8) {
        *(uint32_t*)(Yh + off0 + n8 * 8) = pack2h(o[n8][0] * inv0, o[n8][1] * inv0);
        *(uint32_t*)(Yh + off1 + n8 * 8) = pack2h(o[n8][2] * inv1, o[n8][3] * inv1);
    }
}

// ---------------------------------------------------------------------------
extern "C" void kernel_launch(void* const* d_in, const int* in_sizes, int n_in,
                              void* d_out, int out_size)
{
    (void)in_sizes; (void)n_in; (void)out_size;
    const float* x  = (const float*)d_in[0];
    const float* Wq = (const float*)d_in[1];
    const float* Wk = (const float*)d_in[2];
    const float* Wv = (const float*)d_in[3];
    const float* Wo = (const float*)d_in[4];
    float* out = (float*)d_out;

    unsigned short *qkvh, *qkvl, *xh, *xl, *Bh, *Yh, *Woh;
    cudaGetSymbolAddress((void**)&qkvh, g_QKVh);
    cudaGetSymbolAddress((void**)&qkvl, g_QKVl);
    cudaGetSymbolAddress((void**)&xh, g_xhi);
    cudaGetSymbolAddress((void**)&xl, g_xlo);
    cudaGetSymbolAddress((void**)&Bh, g_Bhi);
    cudaGetSymbolAddress((void**)&Yh, g_Yhi);
    cudaGetSymbolAddress((void**)&Woh, g_Wohi);

    cudaFuncSetAttribute((const void*)gemm_split_mma<true, true>,
                         cudaFuncAttributeMaxDynamicSharedMemorySize, GEMM_SMEM_2A);
    cudaFuncSetAttribute((const void*)gemm_split_mma<false, false>,
                         cudaFuncAttributeMaxDynamicSharedMemorySize, GEMM_SMEM_1A);
    cudaFuncSetAttribute(flash_tc,
                         cudaFuncAttributeMaxDynamicSharedMemorySize, FT_SMEM);

    const int n4x = MTOT * DD / 4;

    // 1) Split x -> fp16 hi/lo
    conv_split<<<n4x / 256, 256>>>((const float4*)x,
        (__half2*)xh, (__half2*)xl, n4x);

    // 2) Transpose+round weights to fp16 hi: fused B [N=1152, K=1024] + Wo^T
    convT_h<<<dim3(32, 32), 256>>>(Wq, 1024, (__half*)Bh, 0);
    convT_h<<<dim3(2, 32),  256>>>(Wk, 64,   (__half*)Bh, 1024);
    convT_h<<<dim3(2, 32),  256>>>(Wv, 64,   (__half*)Bh, 1088);
    convT_h<<<dim3(32, 32), 256>>>(Wo, 1024, (__half*)Woh, 0);

    // 3) Fused QKV projection (2-pass A), epilogue emits fp16 hi/lo
    gemm_split_mma<true, true><<<dim3(NQKV / 128, MTOT / 128), 256, GEMM_SMEM_2A>>>(
        (const __half*)xh, (const __half*)xl, (const __half*)Bh,
        nullptr, (__half*)qkvh, (__half*)qkvl, DD, NQKV);

    // 4) Flash attention -> Yh (fp16 hi only)
    flash_tc<<<dim3(TT / 128, HH, BB), 256, FT_SMEM>>>(
        (const __half*)qkvh, (const __half*)qkvl, (__half*)Yh);

    // 5) Output projection: out = Yh @ Wo (1-pass A, fp32 epilogue)
    gemm_split_mma<false, false><<<dim3(DD / 128, MTOT / 128), 256, GEMM_SMEM_1A>>>(
        (const __half*)Yh, nullptr, (const __half*)Woh,
        out, nullptr, nullptr, DD, DD);
}

// round 12
// speedup vs baseline: 2.4550x; 1.3743x over previous
#include <cuda_runtime.h>
#include <cuda_fp16.h>
#include <cstdint>

// Problem shapes (fixed by the dataset).
#define BB 2
#define TT 2048
#define DD 1024
#define HH 16
#define DKK 64
#define MTOT (BB*TT)     // 4096 rows
#define NQKV 1152        // fused projection width: 1024 Q + 64 K + 64 V

// softmax scale folded with log2(e): 0.125 * 1.4426950408889634
#define SM_SCALE 0.18033688011112042f

// ---------------------------------------------------------------------------
// Device scratch (allocation-free per harness rules).  All fp16, hi-only path.
// ---------------------------------------------------------------------------
__device__ unsigned short g_QKVh[MTOT * NQKV];   // QKV fp16
__device__ unsigned short g_xh[MTOT * DD];       // x fp16
__device__ unsigned short g_Bhi[NQKV * DD];      // [Wq;Wk;Wv]^T fp16
__device__ unsigned short g_Yhi[MTOT * DD];      // Y fp16
__device__ unsigned short g_Wohi[DD * DD];       // Wo^T fp16

// ---------------------------------------------------------------------------
// Generic-PTX tensor helpers (NO arch-'a' features: work on plain sm_103).
// ---------------------------------------------------------------------------
__device__ __forceinline__ uint32_t smem_u32(const void* p) {
    uint32_t a;
    asm("{ .reg .u64 t; cvta.to.shared.u64 t, %1; cvt.u32.u64 %0, t; }"
        : "=r"(a) : "l"(p));
    return a;
}

__device__ __forceinline__ void ldsm_x4(uint32_t& r0, uint32_t& r1,
                                        uint32_t& r2, uint32_t& r3, uint32_t a) {
    asm volatile("ldmatrix.sync.aligned.m8n8.x4.shared.b16 {%0,%1,%2,%3}, [%4];"
                 : "=r"(r0), "=r"(r1), "=r"(r2), "=r"(r3) : "r"(a));
}
__device__ __forceinline__ void ldsm_x4_t(uint32_t& r0, uint32_t& r1,
                                          uint32_t& r2, uint32_t& r3, uint32_t a) {
    asm volatile("ldmatrix.sync.aligned.m8n8.x4.trans.shared.b16 {%0,%1,%2,%3}, [%4];"
                 : "=r"(r0), "=r"(r1), "=r"(r2), "=r"(r3) : "r"(a));
}

// fp16 tensor-core MMA, fp32 accumulate.
__device__ __forceinline__ void mma_f16(float* d, const uint32_t* a,
                                        const uint32_t* b) {
    asm volatile(
        "mma.sync.aligned.m16n8k16.row.col.f32.f16.f16.f32 "
        "{%0,%1,%2,%3}, {%4,%5,%6,%7}, {%8,%9}, {%0,%1,%2,%3};"
        : "+f"(d[0]), "+f"(d[1]), "+f"(d[2]), "+f"(d[3])
        : "r"(a[0]), "r"(a[1]), "r"(a[2]), "r"(a[3]), "r"(b[0]), "r"(b[1]));
}

__device__ __forceinline__ void cp_async16(uint32_t saddr, const void* g) {
    asm volatile("cp.async.cg.shared.global [%0], [%1], 16;" :: "r"(saddr), "l"(g));
}
#define CP_COMMIT() asm volatile("cp.async.commit_group;" ::: "memory")
#define CP_WAIT(n)  asm volatile("cp.async.wait_group %0;" :: "n"(n) : "memory")

// Fast 2^x (single MUFU op).
__device__ __forceinline__ float ex2(float x) {
    float r;
    asm("ex2.approx.ftz.f32 %0, %1;" : "=f"(r) : "f"(x));
    return r;
}

// Round two fp32 to a packed fp16x2.
__device__ __forceinline__ uint32_t pack2h(float a, float b) {
    __half2 H = __floats2half2_rn(a, b);
    return *reinterpret_cast<uint32_t*>(&H);
}

// ---------------------------------------------------------------------------
// Conversion kernels.
// ---------------------------------------------------------------------------
// Elementwise fp32 -> fp16 round (vectorized 4-wide).
__global__ __launch_bounds__(256) void conv_round(
    const float4* __restrict__ a, uint2* __restrict__ oh, int n4)
{
    int i = blockIdx.x * blockDim.x + threadIdx.x;
    if (i >= n4) return;
    float4 v = a[i];
    oh[i] = make_uint2(pack2h(v.x, v.y), pack2h(v.z, v.w));
}

// Transpose + round: W[K=1024, N] row-major -> oh[(n_off+n)*1024 + k] fp16.
__global__ __launch_bounds__(256) void convT_h(
    const float* __restrict__ W, int N,
    __half* __restrict__ oh, int n_off)
{
    __shared__ float t[32][33];
    const int k0 = blockIdx.y * 32, n0 = blockIdx.x * 32;
    const int tx = threadIdx.x & 31, ty = threadIdx.x >> 5;  // 32 x 8
#pragma unroll
    for (int j = 0; j < 4; ++j)
        t[ty + 8*j][tx] = W[(size_t)(k0 + ty + 8*j) * N + n0 + tx];
    __syncthreads();
#pragma unroll
    for (int j = 0; j < 4; ++j) {
        float v = t[tx][ty + 8*j];   // = W[k0+tx][n0+ty+8j]
        oh[(size_t)(n_off + n0 + ty + 8*j) * 1024 + k0 + tx] = __float2half(v);
    }
}

// ---------------------------------------------------------------------------
// fp16 GEMM via mma.sync: C = Ah * Bh^T (single pass, fp32 accum).
// CTA tile 128x128, 8 warps (each 32x64), K-stage 32, cp.async double buffer.
// HALF_OUT: emit fp16 (rounded); else fp32.
// ---------------------------------------------------------------------------
#define ROWB 80                 // 32 fp16 = 64B data + 16B pad
#define ARR_B (128 * ROWB)      // 10240 B
#define STAGE_B (2 * ARR_B)     // 20480 B (Ah, Bh)
#define GEMM_SMEM_BYTES (2 * STAGE_B)   // 40960 B

template<bool HALF_OUT>
__global__ __launch_bounds__(256, 2) void gemm_h(
    const __half* __restrict__ Ah, const __half* __restrict__ Bh,
    float* __restrict__ C, __half* __restrict__ Ch, int Kd, int ldc)
{
    extern __shared__ __align__(16) char smd[];
    const uint32_t sbase = smem_u32(smd);
    const int tid  = threadIdx.x;
    const int lane = tid & 31;
    const int w    = tid >> 5;
    const int m0 = blockIdx.y * 128;
    const int n0 = blockIdx.x * 128;
    const int mw = (w >> 1) * 32;
    const int nw = (w & 1) * 64;

    float acc[2][8][4];
#pragma unroll
    for (int mt = 0; mt < 2; ++mt)
#pragma unroll
        for (int n8 = 0; n8 < 8; ++n8)
#pragma unroll
            for (int q = 0; q < 4; ++q) acc[mt][n8][q] = 0.f;

    const int NS = Kd >> 5;   // K-stages of 32

    // --- stage loader: 1024 x 16B chunks, 4 per thread ---
    auto load_stage = [&](int s) {
        const int kt = s << 5;
        const uint32_t sb = sbase + (s & 1) * STAGE_B;
#pragma unroll
        for (int v = 0; v < 4; ++v) {
            int idx = v * 256 + tid;
            int arr = idx >> 9;          // 0=A, 1=B
            int r   = (idx >> 2) & 127;
            int c   = idx & 3;
            const __half* base = arr ? Bh : Ah;
            int grow = (arr ? n0 : m0) + r;
            cp_async16(sb + arr * ARR_B + r * ROWB + c * 16,
                       base + (size_t)grow * Kd + kt + c * 8);
        }
    };

    load_stage(0);
    CP_COMMIT();

    for (int s = 0; s < NS; ++s) {
        if (s + 1 < NS) { load_stage(s + 1); CP_COMMIT(); CP_WAIT(1); }
        else            { CP_WAIT(0); }
        __syncthreads();

        const uint32_t sb = sbase + (s & 1) * STAGE_B;
        const uint32_t aHb = sb + (mw + (lane & 15)) * ROWB + (lane >> 4) * 16;
        const uint32_t bRow = nw + ((lane >> 4) << 3) + (lane & 7);
        const uint32_t bHb = sb + ARR_B + bRow * ROWB + ((lane >> 3) & 1) * 16;

#pragma unroll
        for (int kk = 0; kk < 2; ++kk) {
            const uint32_t ko = kk * 32;       // 16 halves = 32B
            uint32_t ah[2][4];
            ldsm_x4(ah[0][0], ah[0][1], ah[0][2], ah[0][3], aHb + ko);
            ldsm_x4(ah[1][0], ah[1][1], ah[1][2], ah[1][3], aHb + 16 * ROWB + ko);

            uint32_t bh[8][2];
#pragma unroll
            for (int g = 0; g < 4; ++g)
                ldsm_x4(bh[2*g][0], bh[2*g][1], bh[2*g+1][0], bh[2*g+1][1],
                        bHb + g * 16 * ROWB + ko);
#pragma unroll
            for (int mt = 0; mt < 2; ++mt)
#pragma unroll
                for (int n8 = 0; n8 < 8; ++n8)
                    mma_f16(acc[mt][n8], ah[mt], bh[n8]);
        }
        __syncthreads();
    }

    // Epilogue
#pragma unroll
    for (int mt = 0; mt < 2; ++mt) {
        const int row = m0 + mw + mt * 16 + (lane >> 2);
        const int col = n0 + nw + (lane & 3) * 2;
        if (HALF_OUT) {
            __half* h0 = Ch + (size_t)row * ldc + col;
            __half* h1 = Ch + (size_t)(row + 8) * ldc + col;
#pragma unroll
            for (int n8 = 0; n8 < 8; ++n8) {
                *(uint32_t*)(h0 + n8 * 8) = pack2h(acc[mt][n8][0], acc[mt][n8][1]);
                *(uint32_t*)(h1 + n8 * 8) = pack2h(acc[mt][n8][2], acc[mt][n8][3]);
            }
        } else {
            float* c0 = C + (size_t)row * ldc + col;
            float* c1 = C + (size_t)(row + 8) * ldc + col;
#pragma unroll
            for (int n8 = 0; n8 < 8; ++n8) {
                *(float2*)(c0 + n8 * 8) = make_float2(acc[mt][n8][0], acc[mt][n8][1]);
                *(float2*)(c1 + n8 * 8) = make_float2(acc[mt][n8][2], acc[mt][n8][3]);
            }
        }
    }
}

// ---------------------------------------------------------------------------
// Tensor-core flash attention (causal, multi-query, all-fp16 operands,
// fp32 accum). S = Qh*Kh (1 pass); O += Ph*Vh (1 pass).
// Q tile 128x64 per CTA, 8 warps x 16 rows; softmax register-resident,
// exp in base-2 domain. Y emitted fp16.
// ---------------------------------------------------------------------------
#define FT_ROWB 144
#define FT_ARR  (64 * FT_ROWB)      // 9216 B
#define FT_STG  (2 * FT_ARR)        // Kh, Vh = 18432 B
#define FT_SMEM (2 * FT_STG)        // 36864 B

__global__ __launch_bounds__(256) void flash_tc(
    const __half* __restrict__ QKVh, __half* __restrict__ Yh)
{
    extern __shared__ __align__(16) char smd[];
    const uint32_t sbase = smem_u32(smd);
    const int tid = threadIdx.x, lane = tid & 31, wid = tid >> 5;
    const int h = blockIdx.y, b = blockIdx.z;
    const int qb = (int)gridDim.x - 1 - (int)blockIdx.x;   // longest first
    const int i0 = qb * 128;
    const int g = lane >> 2, qd = lane & 3;

    uint32_t qh[4][4];
    {
        const int r0 = i0 + wid * 16 + g;
        const size_t b0 = (size_t)(b * TT + r0) * NQKV + h * 64;
        const size_t b1 = b0 + (size_t)8 * NQKV;
#pragma unroll
        for (int t = 0; t < 4; ++t) {
            const int c = t * 16 + qd * 2;
            qh[t][0] = *(const uint32_t*)(QKVh + b0 + c);
            qh[t][1] = *(const uint32_t*)(QKVh + b1 + c);
            qh[t][2] = *(const uint32_t*)(QKVh + b0 + c + 8);
            qh[t][3] = *(const uint32_t*)(QKVh + b1 + c + 8);
        }
    }

    float o[8][4];
#pragma unroll
    for (int n8 = 0; n8 < 8; ++n8)
#pragma unroll
        for (int c = 0; c < 4; ++c) o[n8][c] = 0.f;
    float m0 = -1e30f, m1 = -1e30f, l0 = 0.f, l1 = 0.f;

    // --- K/V stage loader: 1024 x 16B chunks, 4 per thread ---
    auto load_kv = [&](int it) {
        const int j0 = it * 64;
        const uint32_t sb = sbase + (it & 1) * FT_STG;
#pragma unroll
        for (int v = 0; v < 4; ++v) {
            int idx = v * 256 + tid;
            int arr = idx >> 9, r = (idx >> 3) & 63, c = idx & 7;   // arr: 0=K,1=V
            int col = (arr == 0 ? 1024 : 1088) + c * 8;
            cp_async16(sb + arr * FT_ARR + r * FT_ROWB + c * 16,
                       QKVh + (size_t)(b * TT + j0 + r) * NQKV + col);
        }
    };

    load_kv(0);
    CP_COMMIT();

    const int nIter = 2 * qb + 2;
    for (int it = 0; it < nIter; ++it) {
        if (it + 1 < nIter) { load_kv(it + 1); CP_COMMIT(); CP_WAIT(1); }
        else                { CP_WAIT(0); }
        __syncthreads();

        const uint32_t sb = sbase + (it & 1) * FT_STG;

        // ---- S = Qh Kh^T ----
        float s[8][4];
#pragma unroll
        for (int n8 = 0; n8 < 8; ++n8)
#pragma unroll
            for (int c = 0; c < 4; ++c) s[n8][c] = 0.f;

        const uint32_t kA = sb + (((lane >> 4) << 3) + (lane & 7)) * FT_ROWB
                          + ((lane >> 3) & 1) * 16;
#pragma unroll
        for (int t = 0; t < 4; ++t) {
            uint32_t kh[8][2];
#pragma unroll
            for (int gg = 0; gg < 4; ++gg)
                ldsm_x4(kh[2*gg][0], kh[2*gg][1], kh[2*gg+1][0], kh[2*gg+1][1],
                        kA + gg * 16 * FT_ROWB + t * 32);
#pragma unroll
            for (int n8 = 0; n8 < 8; ++n8) mma_f16(s[n8], qh[t], kh[n8]);
        }

        // ---- scale (base-2 domain) + causal mask ----
        const int j0 = it * 64;
        const int r0 = i0 + wid * 16 + g;
        const bool msk = (j0 + 63 > i0 + wid * 16);
#pragma unroll
        for (int n8 = 0; n8 < 8; ++n8) {
#pragma unroll
            for (int c = 0; c < 4; ++c) s[n8][c] *= SM_SCALE;
            if (msk) {
                const int j = j0 + n8 * 8 + qd * 2;
                if (j     > r0)     s[n8][0] = -1e30f;
                if (j + 1 > r0)     s[n8][1] = -1e30f;
                if (j     > r0 + 8) s[n8][2] = -1e30f;
                if (j + 1 > r0 + 8) s[n8][3] = -1e30f;
            }
        }

        // ---- online softmax (register-resident, base-2 exp) ----
        float mx0 = -1e30f, mx1 = -1e30f;
#pragma unroll
        for (int n8 = 0; n8 < 8; ++n8) {
            mx0 = fmaxf(mx0, fmaxf(s[n8][0], s[n8][1]));
            mx1 = fmaxf(mx1, fmaxf(s[n8][2], s[n8][3]));
        }
        mx0 = fmaxf(mx0, __shfl_xor_sync(0xffffffffu, mx0, 1));
        mx0 = fmaxf(mx0, __shfl_xor_sync(0xffffffffu, mx0, 2));
        mx1 = fmaxf(mx1, __shfl_xor_sync(0xffffffffu, mx1, 1));
        mx1 = fmaxf(mx1, __shfl_xor_sync(0xffffffffu, mx1, 2));
        const float mn0 = fmaxf(m0, mx0), mn1 = fmaxf(m1, mx1);
        const float sc0 = ex2(m0 - mn0), sc1 = ex2(m1 - mn1);
        m0 = mn0; m1 = mn1;

        float sum0 = 0.f, sum1 = 0.f;
        uint32_t ph[4][4];
#pragma unroll
        for (int t = 0; t < 4; ++t) {
            float p00 = ex2(s[2*t][0] - mn0),   p01 = ex2(s[2*t][1] - mn0);
            float p02 = ex2(s[2*t][2] - mn1),   p03 = ex2(s[2*t][3] - mn1);
            float p10 = ex2(s[2*t+1][0] - mn0), p11 = ex2(s[2*t+1][1] - mn0);
            float p12 = ex2(s[2*t+1][2] - mn1), p13 = ex2(s[2*t+1][3] - mn1);
            sum0 += p00 + p01 + p10 + p11;
            sum1 += p02 + p03 + p12 + p13;
            ph[t][0] = pack2h(p00, p01);
            ph[t][1] = pack2h(p02, p03);
            ph[t][2] = pack2h(p10, p11);
            ph[t][3] = pack2h(p12, p13);
        }
        sum0 += __shfl_xor_sync(0xffffffffu, sum0, 1);
        sum0 += __shfl_xor_sync(0xffffffffu, sum0, 2);
        sum1 += __shfl_xor_sync(0xffffffffu, sum1, 1);
        sum1 += __shfl_xor_sync(0xffffffffu, sum1, 2);
        l0 = l0 * sc0 + sum0;
        l1 = l1 * sc1 + sum1;
#pragma unroll
        for (int n8 = 0; n8 < 8; ++n8) {
            o[n8][0] *= sc0; o[n8][1] *= sc0;
            o[n8][2] *= sc1; o[n8][3] *= sc1;
        }

        // ---- O += Ph Vh ----
        const uint32_t vA = sb + FT_ARR
                          + ((lane & 7) + ((lane >> 3) & 1) * 8) * FT_ROWB
                          + (lane >> 4) * 16;
#pragma unroll
        for (int t = 0; t < 4; ++t) {
            uint32_t vh[8][2];
#pragma unroll
            for (int dg = 0; dg < 4; ++dg)
                ldsm_x4_t(vh[2*dg][0], vh[2*dg][1], vh[2*dg+1][0], vh[2*dg+1][1],
                          vA + t * 16 * FT_ROWB + dg * 32);
#pragma unroll
            for (int n8 = 0; n8 < 8; ++n8) mma_f16(o[n8], ph[t], vh[n8]);
        }
        __syncthreads();
    }

    // ---- epilogue: normalize and write Y as fp16 ----
    const float inv0 = 1.f / l0, inv1 = 1.f / l1;
    const int r0 = i0 + wid * 16 + g;
    const size_t off0 = (size_t)(b * TT + r0) * DD + h * 64 + qd * 2;
    const size_t off1 = off0 + (size_t)8 * DD;
#pragma unroll
    for (int n8 = 0; n8 < 8; ++n8) {
        *(uint32_t*)(Yh + off0 + n8 * 8) = pack2h(o[n8][0] * inv0, o[n8][1] * inv0);
        *(uint32_t*)(Yh + off1 + n8 * 8) = pack2h(o[n8][2] * inv1, o[n8][3] * inv1);
    }
}

// ---------------------------------------------------------------------------
extern "C" void kernel_launch(void* const* d_in, const int* in_sizes, int n_in,
                              void* d_out, int out_size)
{
    (void)in_sizes; (void)n_in; (void)out_size;
    const float* x  = (const float*)d_in[0];
    const float* Wq = (const float*)d_in[1];
    const float* Wk = (const float*)d_in[2];
    const float* Wv = (const float*)d_in[3];
    const float* Wo = (const float*)d_in[4];
    float* out = (float*)d_out;

    unsigned short *qkvh, *xh, *Bh, *Yh, *Woh;
    cudaGetSymbolAddress((void**)&qkvh, g_QKVh);
    cudaGetSymbolAddress((void**)&xh, g_xh);
    cudaGetSymbolAddress((void**)&Bh, g_Bhi);
    cudaGetSymbolAddress((void**)&Yh, g_Yhi);
    cudaGetSymbolAddress((void**)&Woh, g_Wohi);

    cudaFuncSetAttribute((const void*)gemm_h<true>,
                         cudaFuncAttributeMaxDynamicSharedMemorySize, GEMM_SMEM_BYTES);
    cudaFuncSetAttribute((const void*)gemm_h<false>,
                         cudaFuncAttributeMaxDynamicSharedMemorySize, GEMM_SMEM_BYTES);
    cudaFuncSetAttribute(flash_tc,
                         cudaFuncAttributeMaxDynamicSharedMemorySize, FT_SMEM);

    const int n4x = MTOT * DD / 4;

    // 1) Round x -> fp16
    conv_round<<<n4x / 256, 256>>>((const float4*)x, (uint2*)xh, n4x);

    // 2) Transpose+round weights to fp16: fused B [N=1152, K=1024] + Wo^T
    convT_h<<<dim3(32, 32), 256>>>(Wq, 1024, (__half*)Bh, 0);
    convT_h<<<dim3(2, 32),  256>>>(Wk, 64,   (__half*)Bh, 1024);
    convT_h<<<dim3(2, 32),  256>>>(Wv, 64,   (__half*)Bh, 1088);
    convT_h<<<dim3(32, 32), 256>>>(Wo, 1024, (__half*)Woh, 0);

    // 3) Fused QKV projection (fp16 out)
    gemm_h<true><<<dim3(NQKV / 128, MTOT / 128), 256, GEMM_SMEM_BYTES>>>(
        (const __half*)xh, (const __half*)Bh,
        nullptr, (__half*)qkvh, DD, NQKV);

    // 4) Flash attention -> Yh (fp16)
    flash_tc<<<dim3(TT / 128, HH, BB), 256, FT_SMEM>>>(
        (const __half*)qkvh, (__half*)Yh);

    // 5) Output projection: out = Yh @ Wo (fp32 out)
    gemm_h<false><<<dim3(DD / 128, MTOT / 128), 256, GEMM_SMEM_BYTES>>>(
        (const __half*)Yh, (const __half*)Woh,
        out, nullptr, DD, DD);
}

// round 13
// speedup vs baseline: 2.5873x; 1.0539x over previous
#include <cuda_runtime.h>
#include <cuda_fp16.h>
#include <cstdint>

// Problem shapes (fixed by the dataset).
#define BB 2
#define TT 2048
#define DD 1024
#define HH 16
#define DKK 64
#define MTOT (BB*TT)     // 4096 rows
#define NQKV 1152        // fused projection width: 1024 Q + 64 K + 64 V

// softmax scale folded with log2(e): 0.125 * 1.4426950408889634
#define SM_SCALE 0.18033688011112042f

// ---------------------------------------------------------------------------
// Device scratch (allocation-free per harness rules).  All fp16.
// ---------------------------------------------------------------------------
__device__ unsigned short g_QKVh[MTOT * NQKV];   // QKV fp16
__device__ unsigned short g_xh[MTOT * DD];       // x fp16
__device__ unsigned short g_Bhi[NQKV * DD];      // [Wq;Wk;Wv]^T fp16
__device__ unsigned short g_Yhi[MTOT * DD];      // Y fp16
__device__ unsigned short g_Wohi[DD * DD];       // Wo^T fp16

// ---------------------------------------------------------------------------
// Generic-PTX tensor helpers (NO arch-'a' features: work on plain sm_103).
// ---------------------------------------------------------------------------
__device__ __forceinline__ uint32_t smem_u32(const void* p) {
    uint32_t a;
    asm("{ .reg .u64 t; cvta.to.shared.u64 t, %1; cvt.u32.u64 %0, t; }"
        : "=r"(a) : "l"(p));
    return a;
}

__device__ __forceinline__ void ldsm_x4(uint32_t& r0, uint32_t& r1,
                                        uint32_t& r2, uint32_t& r3, uint32_t a) {
    asm volatile("ldmatrix.sync.aligned.m8n8.x4.shared.b16 {%0,%1,%2,%3}, [%4];"
                 : "=r"(r0), "=r"(r1), "=r"(r2), "=r"(r3) : "r"(a));
}
__device__ __forceinline__ void ldsm_x4_t(uint32_t& r0, uint32_t& r1,
                                          uint32_t& r2, uint32_t& r3, uint32_t a) {
    asm volatile("ldmatrix.sync.aligned.m8n8.x4.trans.shared.b16 {%0,%1,%2,%3}, [%4];"
                 : "=r"(r0), "=r"(r1), "=r"(r2), "=r"(r3) : "r"(a));
}

// fp16 tensor-core MMA, fp32 accumulate.
__device__ __forceinline__ void mma_f16(float* d, const uint32_t* a,
                                        const uint32_t* b) {
    asm volatile(
        "mma.sync.aligned.m16n8k16.row.col.f32.f16.f16.f32 "
        "{%0,%1,%2,%3}, {%4,%5,%6,%7}, {%8,%9}, {%0,%1,%2,%3};"
        : "+f"(d[0]), "+f"(d[1]), "+f"(d[2]), "+f"(d[3])
        : "r"(a[0]), "r"(a[1]), "r"(a[2]), "r"(a[3]), "r"(b[0]), "r"(b[1]));
}

__device__ __forceinline__ void cp_async16(uint32_t saddr, const void* g) {
    asm volatile("cp.async.cg.shared.global [%0], [%1], 16;" :: "r"(saddr), "l"(g));
}
#define CP_COMMIT() asm volatile("cp.async.commit_group;" ::: "memory")
#define CP_WAIT(n)  asm volatile("cp.async.wait_group %0;" :: "n"(n) : "memory")

// Fast 2^x (single MUFU op).
__device__ __forceinline__ float ex2(float x) {
    float r;
    asm("ex2.approx.ftz.f32 %0, %1;" : "=f"(r) : "f"(x));
    return r;
}

// Round two fp32 to a packed fp16x2.
__device__ __forceinline__ uint32_t pack2h(float a, float b) {
    __half2 H = __floats2half2_rn(a, b);
    return *reinterpret_cast<uint32_t*>(&H);
}

// ---------------------------------------------------------------------------
// Conversion kernels.
// ---------------------------------------------------------------------------
// Elementwise fp32 -> fp16 round (vectorized 4-wide).
__global__ __launch_bounds__(256) void conv_round(
    const float4* __restrict__ a, uint2* __restrict__ oh, int n4)
{
    int i = blockIdx.x * blockDim.x + threadIdx.x;
    if (i >= n4) return;
    float4 v = a[i];
    oh[i] = make_uint2(pack2h(v.x, v.y), pack2h(v.z, v.w));
}

// Fused transpose+round for ALL weights. blockIdx.z selects the tensor:
//   0: Wq [1024,1024] -> Bh  @ n_off 0
//   1: Wk [1024,  64] -> Bh  @ n_off 1024
//   2: Wv [1024,  64] -> Bh  @ n_off 1088
//   3: Wo [1024,1024] -> Woh @ n_off 0
__global__ __launch_bounds__(256) void convW_all(
    const float* __restrict__ Wq, const float* __restrict__ Wk,
    const float* __restrict__ Wv, const float* __restrict__ Wo,
    __half* __restrict__ Bh, __half* __restrict__ Woh)
{
    const int z = blockIdx.z;
    const float* W;
    __half* oh;
    int N, n_off;
    if      (z == 0) { W = Wq; oh = Bh;  N = 1024; n_off = 0;    }
    else if (z == 1) { W = Wk; oh = Bh;  N = 64;   n_off = 1024; }
    else if (z == 2) { W = Wv; oh = Bh;  N = 64;   n_off = 1088; }
    else             { W = Wo; oh = Woh; N = 1024; n_off = 0;    }
    if ((int)blockIdx.x * 32 >= N) return;

    __shared__ float t[32][33];
    const int k0 = blockIdx.y * 32, n0 = blockIdx.x * 32;
    const int tx = threadIdx.x & 31, ty = threadIdx.x >> 5;  // 32 x 8
#pragma unroll
    for (int j = 0; j < 4; ++j)
        t[ty + 8*j][tx] = W[(size_t)(k0 + ty + 8*j) * N + n0 + tx];
    __syncthreads();
#pragma unroll
    for (int j = 0; j < 4; ++j) {
        float v = t[tx][ty + 8*j];   // = W[k0+tx][n0+ty+8j]
        oh[(size_t)(n_off + n0 + ty + 8*j) * 1024 + k0 + tx] = __float2half(v);
    }
}

// ---------------------------------------------------------------------------
// fp16 GEMM via mma.sync: C = Ah * Bh^T (fp32 accum).
// CTA tile 128x128, 8 warps (each 32x64), K-stage 64, cp.async double buffer,
// 2 CTAs/SM (smem 73728 x2 = 147KB). HALF_OUT: emit fp16; else fp32.
// ---------------------------------------------------------------------------
#define ROWB 144                // 64 fp16 = 128B data + 16B pad
#define ARR_B (128 * ROWB)      // 18432 B
#define STAGE_B (2 * ARR_B)     // 36864 B (Ah, Bh)
#define GEMM_SMEM_BYTES (2 * STAGE_B)   // 73728 B

template<bool HALF_OUT>
__global__ __launch_bounds__(256, 2) void gemm_h(
    const __half* __restrict__ Ah, const __half* __restrict__ Bh,
    float* __restrict__ C, __half* __restrict__ Ch, int Kd, int ldc)
{
    extern __shared__ __align__(16) char smd[];
    const uint32_t sbase = smem_u32(smd);
    const int tid  = threadIdx.x;
    const int lane = tid & 31;
    const int w    = tid >> 5;
    const int m0 = blockIdx.y * 128;
    const int n0 = blockIdx.x * 128;
    const int mw = (w >> 1) * 32;
    const int nw = (w & 1) * 64;

    float acc[2][8][4];
#pragma unroll
    for (int mt = 0; mt < 2; ++mt)
#pragma unroll
        for (int n8 = 0; n8 < 8; ++n8)
#pragma unroll
            for (int q = 0; q < 4; ++q) acc[mt][n8][q] = 0.f;

    const int NS = Kd >> 6;   // K-stages of 64

    // --- stage loader: 2048 x 16B chunks, 8 per thread ---
    auto load_stage = [&](int s) {
        const int kt = s << 6;
        const uint32_t sb = sbase + (s & 1) * STAGE_B;
#pragma unroll
        for (int v = 0; v < 8; ++v) {
            int idx = v * 256 + tid;
            int arr = idx >> 10;         // 0=A, 1=B
            int r   = (idx >> 3) & 127;
            int c   = idx & 7;
            const __half* base = arr ? Bh : Ah;
            int grow = (arr ? n0 : m0) + r;
            cp_async16(sb + arr * ARR_B + r * ROWB + c * 16,
                       base + (size_t)grow * Kd + kt + c * 8);
        }
    };

    load_stage(0);
    CP_COMMIT();

    for (int s = 0; s < NS; ++s) {
        if (s + 1 < NS) { load_stage(s + 1); CP_COMMIT(); CP_WAIT(1); }
        else            { CP_WAIT(0); }
        __syncthreads();

        const uint32_t sb = sbase + (s & 1) * STAGE_B;
        const uint32_t aHb = sb + (mw + (lane & 15)) * ROWB + (lane >> 4) * 16;
        const uint32_t bRow = nw + ((lane >> 4) << 3) + (lane & 7);
        const uint32_t bHb = sb + ARR_B + bRow * ROWB + ((lane >> 3) & 1) * 16;

#pragma unroll
        for (int kk = 0; kk < 4; ++kk) {
            const uint32_t ko = kk * 32;       // 16 halves = 32B per k16 step
            uint32_t ah[2][4];
            ldsm_x4(ah[0][0], ah[0][1], ah[0][2], ah[0][3], aHb + ko);
            ldsm_x4(ah[1][0], ah[1][1], ah[1][2], ah[1][3], aHb + 16 * ROWB + ko);

            uint32_t bh[8][2];
#pragma unroll
            for (int g = 0; g < 4; ++g)
                ldsm_x4(bh[2*g][0], bh[2*g][1], bh[2*g+1][0], bh[2*g+1][1],
                        bHb + g * 16 * ROWB + ko);
#pragma unroll
            for (int mt = 0; mt < 2; ++mt)
#pragma unroll
                for (int n8 = 0; n8 < 8; ++n8)
                    mma_f16(acc[mt][n8], ah[mt], bh[n8]);
        }
        __syncthreads();
    }

    // Epilogue
#pragma unroll
    for (int mt = 0; mt < 2; ++mt) {
        const int row = m0 + mw + mt * 16 + (lane >> 2);
        const int col = n0 + nw + (lane & 3) * 2;
        if (HALF_OUT) {
            __half* h0 = Ch + (size_t)row * ldc + col;
            __half* h1 = Ch + (size_t)(row + 8) * ldc + col;
#pragma unroll
            for (int n8 = 0; n8 < 8; ++n8) {
                *(uint32_t*)(h0 + n8 * 8) = pack2h(acc[mt][n8][0], acc[mt][n8][1]);
                *(uint32_t*)(h1 + n8 * 8) = pack2h(acc[mt][n8][2], acc[mt][n8][3]);
            }
        } else {
            float* c0 = C + (size_t)row * ldc + col;
            float* c1 = C + (size_t)(row + 8) * ldc + col;
#pragma unroll
            for (int n8 = 0; n8 < 8; ++n8) {
                *(float2*)(c0 + n8 * 8) = make_float2(acc[mt][n8][0], acc[mt][n8][1]);
                *(float2*)(c1 + n8 * 8) = make_float2(acc[mt][n8][2], acc[mt][n8][3]);
            }
        }
    }
}

// ---------------------------------------------------------------------------
// Tensor-core flash attention (causal, multi-query, all-fp16 operands,
// fp32 accum). S = Qh*Kh; O += Ph*Vh. 3-stage cp.async ring, ONE barrier
// per iteration (loads issued post-barrier -> race-free buffer reuse).
// Per-lane partial row-sums; quad-reduced once in the epilogue.
// ---------------------------------------------------------------------------
#define FT_ROWB 144
#define FT_ARR  (64 * FT_ROWB)      // 9216 B
#define FT_STG  (2 * FT_ARR)        // Kh, Vh = 18432 B
#define FT_SMEM (3 * FT_STG)        // 55296 B (3-stage ring)

__global__ __launch_bounds__(256) void flash_tc(
    const __half* __restrict__ QKVh, __half* __restrict__ Yh)
{
    extern __shared__ __align__(16) char smd[];
    const uint32_t sbase = smem_u32(smd);
    const int tid = threadIdx.x, lane = tid & 31, wid = tid >> 5;
    const int h = blockIdx.y, b = blockIdx.z;
    const int qb = (int)gridDim.x - 1 - (int)blockIdx.x;   // longest first
    const int i0 = qb * 128;
    const int g = lane >> 2, qd = lane & 3;

    uint32_t qh[4][4];
    {
        const int r0 = i0 + wid * 16 + g;
        const size_t b0 = (size_t)(b * TT + r0) * NQKV + h * 64;
        const size_t b1 = b0 + (size_t)8 * NQKV;
#pragma unroll
        for (int t = 0; t < 4; ++t) {
            const int c = t * 16 + qd * 2;
            qh[t][0] = *(const uint32_t*)(QKVh + b0 + c);
            qh[t][1] = *(const uint32_t*)(QKVh + b1 + c);
            qh[t][2] = *(const uint32_t*)(QKVh + b0 + c + 8);
            qh[t][3] = *(const uint32_t*)(QKVh + b1 + c + 8);
        }
    }

    float o[8][4];
#pragma unroll
    for (int n8 = 0; n8 < 8; ++n8)
#pragma unroll
        for (int c = 0; c < 4; ++c) o[n8][c] = 0.f;
    float m0 = -1e30f, m1 = -1e30f, l0 = 0.f, l1 = 0.f;   // l: per-lane partial

    // --- K/V stage loader: 1024 x 16B chunks, 4 per thread; ring of 3 ---
    auto load_kv = [&](int it) {
        const int j0 = it * 64;
        const uint32_t sb = sbase + (it % 3) * FT_STG;
#pragma unroll
        for (int v = 0; v < 4; ++v) {
            int idx = v * 256 + tid;
            int arr = idx >> 9, r = (idx >> 3) & 63, c = idx & 7;   // arr: 0=K,1=V
            int col = (arr == 0 ? 1024 : 1088) + c * 8;
            cp_async16(sb + arr * FT_ARR + r * FT_ROWB + c * 16,
                       QKVh + (size_t)(b * TT + j0 + r) * NQKV + col);
        }
    };

    const int nIter = 2 * qb + 2;     // always >= 2
    load_kv(0); CP_COMMIT();
    load_kv(1); CP_COMMIT();

    for (int it = 0; it < nIter; ++it) {
        if (it + 1 < nIter) { CP_WAIT(1); }   // buffer `it` landed
        else                { CP_WAIT(0); }
        __syncthreads();                       // visibility + buffer-reuse safety
        if (it + 2 < nIter) { load_kv(it + 2); CP_COMMIT(); }

        const uint32_t sb = sbase + (it % 3) * FT_STG;

        // ---- S = Qh Kh^T ----
        float s[8][4];
#pragma unroll
        for (int n8 = 0; n8 < 8; ++n8)
#pragma unroll
            for (int c = 0; c < 4; ++c) s[n8][c] = 0.f;

        const uint32_t kA = sb + (((lane >> 4) << 3) + (lane & 7)) * FT_ROWB
                          + ((lane >> 3) & 1) * 16;
#pragma unroll
        for (int t = 0; t < 4; ++t) {
            uint32_t kh[8][2];
#pragma unroll
            for (int gg = 0; gg < 4; ++gg)
                ldsm_x4(kh[2*gg][0], kh[2*gg][1], kh[2*gg+1][0], kh[2*gg+1][1],
                        kA + gg * 16 * FT_ROWB + t * 32);
#pragma unroll
            for (int n8 = 0; n8 < 8; ++n8) mma_f16(s[n8], qh[t], kh[n8]);
        }

        // ---- scale (base-2 domain) + causal mask ----
        const int j0 = it * 64;
        const int r0 = i0 + wid * 16 + g;
        const bool msk = (j0 + 63 > i0 + wid * 16);
#pragma unroll
        for (int n8 = 0; n8 < 8; ++n8) {
#pragma unroll
            for (int c = 0; c < 4; ++c) s[n8][c] *= SM_SCALE;
            if (msk) {
                const int j = j0 + n8 * 8 + qd * 2;
                if (j     > r0)     s[n8][0] = -1e30f;
                if (j + 1 > r0)     s[n8][1] = -1e30f;
                if (j     > r0 + 8) s[n8][2] = -1e30f;
                if (j + 1 > r0 + 8) s[n8][3] = -1e30f;
            }
        }

        // ---- online softmax (register-resident, base-2 exp) ----
        float mx0 = -1e30f, mx1 = -1e30f;
#pragma unroll
        for (int n8 = 0; n8 < 8; ++n8) {
            mx0 = fmaxf(mx0, fmaxf(s[n8][0], s[n8][1]));
            mx1 = fmaxf(mx1, fmaxf(s[n8][2], s[n8][3]));
        }
        mx0 = fmaxf(mx0, __shfl_xor_sync(0xffffffffu, mx0, 1));
        mx0 = fmaxf(mx0, __shfl_xor_sync(0xffffffffu, mx0, 2));
        mx1 = fmaxf(mx1, __shfl_xor_sync(0xffffffffu, mx1, 1));
        mx1 = fmaxf(mx1, __shfl_xor_sync(0xffffffffu, mx1, 2));
        const float mn0 = fmaxf(m0, mx0), mn1 = fmaxf(m1, mx1);
        const float sc0 = ex2(m0 - mn0), sc1 = ex2(m1 - mn1);
        m0 = mn0; m1 = mn1;

        float sum0 = 0.f, sum1 = 0.f;
        uint32_t ph[4][4];
#pragma unroll
        for (int t = 0; t < 4; ++t) {
            float p00 = ex2(s[2*t][0] - mn0),   p01 = ex2(s[2*t][1] - mn0);
            float p02 = ex2(s[2*t][2] - mn1),   p03 = ex2(s[2*t][3] - mn1);
            float p10 = ex2(s[2*t+1][0] - mn0), p11 = ex2(s[2*t+1][1] - mn0);
            float p12 = ex2(s[2*t+1][2] - mn1), p13 = ex2(s[2*t+1][3] - mn1);
            sum0 += p00 + p01 + p10 + p11;
            sum1 += p02 + p03 + p12 + p13;
            ph[t][0] = pack2h(p00, p01);
            ph[t][1] = pack2h(p02, p03);
            ph[t][2] = pack2h(p10, p11);
            ph[t][3] = pack2h(p12, p13);
        }
        // per-lane partial l (sc uniform across quad; reduce once at the end)
        l0 = l0 * sc0 + sum0;
        l1 = l1 * sc1 + sum1;
#pragma unroll
        for (int n8 = 0; n8 < 8; ++n8) {
            o[n8][0] *= sc0; o[n8][1] *= sc0;
            o[n8][2] *= sc1; o[n8][3] *= sc1;
        }

        // ---- O += Ph Vh ----
        const uint32_t vA = sb + FT_ARR
                          + ((lane & 7) + ((lane >> 3) & 1) * 8) * FT_ROWB
                          + (lane >> 4) * 16;
#pragma unroll
        for (int t = 0; t < 4; ++t) {
            uint32_t vh[8][2];
#pragma unroll
            for (int dg = 0; dg < 4; ++dg)
                ldsm_x4_t(vh[2*dg][0], vh[2*dg][1], vh[2*dg+1][0], vh[2*dg+1][1],
                          vA + t * 16 * FT_ROWB + dg * 32);
#pragma unroll
            for (int n8 = 0; n8 < 8; ++n8) mma_f16(o[n8], ph[t], vh[n8]);
        }
        // no trailing barrier: next-iter barrier precedes any buffer overwrite
    }

    // ---- epilogue: reduce l across quad, normalize, write fp16 ----
    l0 += __shfl_xor_sync(0xffffffffu, l0, 1);
    l0 += __shfl_xor_sync(0xffffffffu, l0, 2);
    l1 += __shfl_xor_sync(0xffffffffu, l1, 1);
    l1 += __shfl_xor_sync(0xffffffffu, l1, 2);
    const float inv0 = 1.f / l0, inv1 = 1.f / l1;
    const int r0 = i0 + wid * 16 + g;
    const size_t off0 = (size_t)(b * TT + r0) * DD + h * 64 + qd * 2;
    const size_t off1 = off0 + (size_t)8 * DD;
#pragma unroll
    for (int n8 = 0; n8 < 8; ++n8) {
        *(uint32_t*)(Yh + off0 + n8 * 8) = pack2h(o[n8][0] * inv0, o[n8][1] * inv0);
        *(uint32_t*)(Yh + off1 + n8 * 8) = pack2h(o[n8][2] * inv1, o[n8][3] * inv1);
    }
}

// ---------------------------------------------------------------------------
extern "C" void kernel_launch(void* const* d_in, const int* in_sizes, int n_in,
                              void* d_out, int out_size)
{
    (void)in_sizes; (void)n_in; (void)out_size;
    const float* x  = (const float*)d_in[0];
    const float* Wq = (const float*)d_in[1];
    const float* Wk = (const float*)d_in[2];
    const float* Wv = (const float*)d_in[3];
    const float* Wo = (const float*)d_in[4];
    float* out = (float*)d_out;

    unsigned short *qkvh, *xh, *Bh, *Yh, *Woh;
    cudaGetSymbolAddress((void**)&qkvh, g_QKVh);
    cudaGetSymbolAddress((void**)&xh, g_xh);
    cudaGetSymbolAddress((void**)&Bh, g_Bhi);
    cudaGetSymbolAddress((void**)&Yh, g_Yhi);
    cudaGetSymbolAddress((void**)&Woh, g_Wohi);

    cudaFuncSetAttribute((const void*)gemm_h<true>,
                         cudaFuncAttributeMaxDynamicSharedMemorySize, GEMM_SMEM_BYTES);
    cudaFuncSetAttribute((const void*)gemm_h<false>,
                         cudaFuncAttributeMaxDynamicSharedMemorySize, GEMM_SMEM_BYTES);
    cudaFuncSetAttribute(flash_tc,
                         cudaFuncAttributeMaxDynamicSharedMemorySize, FT_SMEM);

    const int n4x = MTOT * DD / 4;

    // 1) Round x -> fp16
    conv_round<<<n4x / 256, 256>>>((const float4*)x, (uint2*)xh, n4x);

    // 2) All weight transpose+round in ONE launch
    convW_all<<<dim3(32, 32, 4), 256>>>(Wq, Wk, Wv, Wo,
                                        (__half*)Bh, (__half*)Woh);

    // 3) Fused QKV projection (fp16 out)
    gemm_h<true><<<dim3(NQKV / 128, MTOT / 128), 256, GEMM_SMEM_BYTES>>>(
        (const __half*)xh, (const __half*)Bh,
        nullptr, (__half*)qkvh, DD, NQKV);

    // 4) Flash attention -> Yh (fp16)
    flash_tc<<<dim3(TT / 128, HH, BB), 256, FT_SMEM>>>(
        (const __half*)qkvh, (__half*)Yh);

    // 5) Output projection: out = Yh @ Wo (fp32 out)
    gemm_h<false><<<dim3(DD / 128, MTOT / 128), 256, GEMM_SMEM_BYTES>>>(
        (const __half*)Yh, (const __half*)Woh,
        out, nullptr, DD, DD);
}